// round 1
// baseline (speedup 1.0000x reference)
#include <cuda_runtime.h>
#include <math.h>

#define TT 8192
#define DD 1024
#define HH 2048
#define EE 8

// ---------------- scratch (device globals: allocation-free) ----------------
__device__ int   g_expert[TT];
__device__ int   g_pos[TT];
__device__ float g_prob[TT];
__device__ int   g_counts[EE];
__device__ int   g_off[EE + 1];
__device__ int   g_perm[TT];
__device__ float g_Xg[TT * DD];   // 32 MB gathered tokens
__device__ float g_Hg[TT * HH];   // 64 MB hidden activations

// ---------------- tiny setup kernels ----------------
__global__ void zero_counts_kernel() {
    if (threadIdx.x < EE) g_counts[threadIdx.x] = 0;
}

// fp32 router: 1 warp per token. logits = x[t] . Wr[:,e] + br[e]; softmax; top-1.
__global__ void router_kernel(const float* __restrict__ x,
                              const float* __restrict__ Wr,
                              const float* __restrict__ br) {
    int token = blockIdx.x * 8 + (threadIdx.x >> 5);
    int lane  = threadIdx.x & 31;
    const float* xr = x + (size_t)token * DD;
    float acc[EE];
#pragma unroll
    for (int e = 0; e < EE; e++) acc[e] = 0.f;
    for (int d = lane; d < DD; d += 32) {
        float xv = xr[d];
        const float4* w = (const float4*)(Wr + d * EE);
        float4 w0 = w[0], w1 = w[1];
        acc[0] += xv * w0.x; acc[1] += xv * w0.y;
        acc[2] += xv * w0.z; acc[3] += xv * w0.w;
        acc[4] += xv * w1.x; acc[5] += xv * w1.y;
        acc[6] += xv * w1.z; acc[7] += xv * w1.w;
    }
#pragma unroll
    for (int e = 0; e < EE; e++) {
#pragma unroll
        for (int o = 16; o; o >>= 1) acc[e] += __shfl_xor_sync(0xffffffffu, acc[e], o);
    }
    if (lane == 0) {
        float m = -1e30f; int best = 0;
#pragma unroll
        for (int e = 0; e < EE; e++) {
            float l = acc[e] + br[e];
            acc[e] = l;
            if (l > m) { m = l; best = e; }   // strict > keeps first max (matches argmax)
        }
        float s = 0.f;
#pragma unroll
        for (int e = 0; e < EE; e++) s += expf(acc[e] - m);
        g_expert[token] = best;
        g_prob[token]   = 1.f / s;            // softmax value at the argmax
        g_pos[token]    = atomicAdd(&g_counts[best], 1);
    }
}

__global__ void scan_kernel() {
    int s = 0;
#pragma unroll
    for (int e = 0; e < EE; e++) { g_off[e] = s; s += g_counts[e]; }
    g_off[EE] = s;
}

// gather token rows into expert-contiguous Xg, record perm
__global__ void gather_kernel(const float* __restrict__ x) {
    int token = blockIdx.x;
    int dst = g_off[g_expert[token]] + g_pos[token];
    if (threadIdx.x == 0) g_perm[dst] = token;
    const float4* s = (const float4*)(x + (size_t)token * DD);
    float4* d = (float4*)(g_Xg + (size_t)dst * DD);
    for (int i = threadIdx.x; i < DD / 4; i += blockDim.x) d[i] = s[i];
}

// ---------------- grouped SGEMM: 128x128 tile, BK=8, 8x8 microtile ----------------
// C[rows, N] = A[rows, K] @ W[e][K, N] (+bias, optional relu, optional scatter*prob)
template <int N, bool RELU, bool SCATTER>
__global__ void __launch_bounds__(256, 2) gemm_grouped(
    const float* __restrict__ A, const float* __restrict__ Wall,
    const float* __restrict__ ball, float* __restrict__ C, int K)
{
    int e = blockIdx.z;
    int rowBeg = g_off[e], rowEnd = g_off[e + 1];
    int row0 = rowBeg + blockIdx.y * 128;
    if (row0 >= rowEnd) return;
    int n0 = blockIdx.x * 128;

    const float* B    = Wall + (size_t)e * K * N;
    const float* bias = ball + (size_t)e * N;

    __shared__ float As[8][132];   // padded: conflict-free transposed stores
    __shared__ float Bs[8][128];

    int tid = threadIdx.x;
    int tx = tid & 15, ty = tid >> 4;

    float acc[8][8];
#pragma unroll
    for (int i = 0; i < 8; i++)
#pragma unroll
        for (int j = 0; j < 8; j++) acc[i][j] = 0.f;

    int arow = tid >> 1;           // 0..127
    int akq  = (tid & 1) * 4;      // 0 or 4
    int brow = tid >> 5;           // 0..7
    int bcol = (tid & 31) * 4;     // 0..124

    const float* Aptr = A + (size_t)(row0 + arow) * K + akq;
    bool aValid = (row0 + arow) < rowEnd;
    const float* Bptr = B + (size_t)brow * N + n0 + bcol;

    for (int k0 = 0; k0 < K; k0 += 8) {
        float4 av = aValid ? *(const float4*)(Aptr + k0) : make_float4(0.f, 0.f, 0.f, 0.f);
        float4 bv = *(const float4*)(Bptr + (size_t)k0 * N);
        __syncthreads();
        As[akq + 0][arow] = av.x; As[akq + 1][arow] = av.y;
        As[akq + 2][arow] = av.z; As[akq + 3][arow] = av.w;
        *(float4*)&Bs[brow][bcol] = bv;
        __syncthreads();
#pragma unroll
        for (int k = 0; k < 8; k++) {
            float a[8], b[8];
            *(float4*)&a[0] = *(const float4*)&As[k][ty * 8];
            *(float4*)&a[4] = *(const float4*)&As[k][ty * 8 + 4];
            *(float4*)&b[0] = *(const float4*)&Bs[k][tx * 8];
            *(float4*)&b[4] = *(const float4*)&Bs[k][tx * 8 + 4];
#pragma unroll
            for (int i = 0; i < 8; i++)
#pragma unroll
                for (int j = 0; j < 8; j++) acc[i][j] = fmaf(a[i], b[j], acc[i][j]);
        }
    }

    int ncol = n0 + tx * 8;
    float bl[8];
#pragma unroll
    for (int j = 0; j < 8; j++) bl[j] = bias[ncol + j];

#pragma unroll
    for (int i = 0; i < 8; i++) {
        int row = row0 + ty * 8 + i;
        if (row < rowEnd) {
            float scale = 1.f;
            float* cdst;
            if (SCATTER) {
                int tok = g_perm[row];
                scale = g_prob[tok];
                cdst = C + (size_t)tok * N + ncol;
            } else {
                cdst = C + (size_t)row * N + ncol;
            }
            float out[8];
#pragma unroll
            for (int j = 0; j < 8; j++) {
                float v = acc[i][j] + bl[j];
                if (RELU) v = fmaxf(v, 0.f);
                if (SCATTER) v *= scale;
                out[j] = v;
            }
            *(float4*)&cdst[0] = *(float4*)&out[0];
            *(float4*)&cdst[4] = *(float4*)&out[4];
        }
    }
}

// ---------------- entry ----------------
extern "C" void kernel_launch(void* const* d_in, const int* in_sizes, int n_in,
                              void* d_out, int out_size) {
    const float* x  = (const float*)d_in[0];
    const float* Wr = (const float*)d_in[1];
    const float* br = (const float*)d_in[2];
    const float* W1 = (const float*)d_in[3];
    const float* b1 = (const float*)d_in[4];
    const float* W2 = (const float*)d_in[5];
    const float* b2 = (const float*)d_in[6];
    float* out = (float*)d_out;

    float *Xg = nullptr, *Hg = nullptr;
    cudaGetSymbolAddress((void**)&Xg, g_Xg);
    cudaGetSymbolAddress((void**)&Hg, g_Hg);

    zero_counts_kernel<<<1, 32>>>();
    router_kernel<<<TT / 8, 256>>>(x, Wr, br);
    scan_kernel<<<1, 1>>>();
    gather_kernel<<<TT, 256>>>(x);

    dim3 g1(HH / 128, TT / 128, EE);
    gemm_grouped<HH, true,  false><<<g1, 256>>>(Xg, W1, b1, Hg, DD);
    dim3 g2(DD / 128, TT / 128, EE);
    gemm_grouped<DD, false, true ><<<g2, 256>>>(Hg, W2, b2, out, HH);
}

// round 3
// speedup vs baseline: 2.3245x; 2.3245x over previous
#include <cuda_runtime.h>
#include <cuda_bf16.h>
#include <math.h>
#include <stdint.h>

#define TT 8192
#define DD 1024
#define HH 2048
#define EE 8
#define PAD 256   // row padding so out-of-segment tile rows stay in-bounds

// ---------------- scratch (device globals: allocation-free) ----------------
__device__ int   g_expert[TT];
__device__ int   g_pos[TT];
__device__ float g_prob[TT];
__device__ int   g_counts[EE];
__device__ int   g_off[EE + 1];
__device__ int   g_perm[TT];

__device__ __nv_bfloat16 g_Xh[(TT + PAD) * DD];
__device__ __nv_bfloat16 g_Xl[(TT + PAD) * DD];
__device__ __nv_bfloat16 g_Hh[(TT + PAD) * HH];
__device__ __nv_bfloat16 g_Hl[(TT + PAD) * HH];
__device__ __nv_bfloat16 g_W1h[EE * HH * DD];  // W1^T: [E][H][D]
__device__ __nv_bfloat16 g_W1l[EE * HH * DD];
__device__ __nv_bfloat16 g_W2h[EE * DD * HH];  // W2^T: [E][D][H]
__device__ __nv_bfloat16 g_W2l[EE * DD * HH];

// ---------------- PTX helpers (plain compute_103-safe: sm_80-era ops only) ----
__device__ __forceinline__ uint32_t smem_u32(const void* p) {
    uint32_t a;
    asm("{ .reg .u64 t; cvta.to.shared.u64 t, %1; cvt.u32.u64 %0, t; }" : "=r"(a) : "l"(p));
    return a;
}
__device__ __forceinline__ void cp16(uint32_t dst, const void* src) {
    asm volatile("cp.async.cg.shared.global [%0], [%1], 16;" :: "r"(dst), "l"(src) : "memory");
}
__device__ __forceinline__ void cp_commit() { asm volatile("cp.async.commit_group;" ::: "memory"); }
__device__ __forceinline__ void cp_wait0()  { asm volatile("cp.async.wait_group 0;" ::: "memory"); }
__device__ __forceinline__ void cp_wait1()  { asm volatile("cp.async.wait_group 1;" ::: "memory"); }

#define LDSM4(r0, r1, r2, r3, addr) \
    asm volatile("ldmatrix.sync.aligned.m8n8.x4.shared.b16 {%0,%1,%2,%3}, [%4];" \
        : "=r"(r0), "=r"(r1), "=r"(r2), "=r"(r3) : "r"(addr))

#define MMA16816(d, a, b0v, b1v) \
    asm volatile("mma.sync.aligned.m16n8k16.row.col.f32.bf16.bf16.f32 " \
        "{%0,%1,%2,%3}, {%4,%5,%6,%7}, {%8,%9}, {%0,%1,%2,%3};" \
        : "+f"((d)[0]), "+f"((d)[1]), "+f"((d)[2]), "+f"((d)[3]) \
        : "r"((a)[0]), "r"((a)[1]), "r"((a)[2]), "r"((a)[3]), "r"(b0v), "r"(b1v))

// ---------------- tiny setup kernels ----------------
__global__ void zero_counts_kernel() {
    if (threadIdx.x < EE) g_counts[threadIdx.x] = 0;
}

// fp32 router: 1 warp per token (exact, so argmax matches reference)
__global__ void router_kernel(const float* __restrict__ x,
                              const float* __restrict__ Wr,
                              const float* __restrict__ br) {
    int token = blockIdx.x * 8 + (threadIdx.x >> 5);
    int lane  = threadIdx.x & 31;
    const float* xr = x + (size_t)token * DD;
    float acc[EE];
#pragma unroll
    for (int e = 0; e < EE; e++) acc[e] = 0.f;
    for (int d = lane; d < DD; d += 32) {
        float xv = xr[d];
        const float4* w = (const float4*)(Wr + d * EE);
        float4 w0 = w[0], w1 = w[1];
        acc[0] += xv * w0.x; acc[1] += xv * w0.y;
        acc[2] += xv * w0.z; acc[3] += xv * w0.w;
        acc[4] += xv * w1.x; acc[5] += xv * w1.y;
        acc[6] += xv * w1.z; acc[7] += xv * w1.w;
    }
#pragma unroll
    for (int e = 0; e < EE; e++) {
#pragma unroll
        for (int o = 16; o; o >>= 1) acc[e] += __shfl_xor_sync(0xffffffffu, acc[e], o);
    }
    if (lane == 0) {
        float m = -1e30f; int best = 0;
#pragma unroll
        for (int e = 0; e < EE; e++) {
            float l = acc[e] + br[e];
            acc[e] = l;
            if (l > m) { m = l; best = e; }
        }
        float s = 0.f;
#pragma unroll
        for (int e = 0; e < EE; e++) s += expf(acc[e] - m);
        g_expert[token] = best;
        g_prob[token]   = 1.f / s;
        g_pos[token]    = atomicAdd(&g_counts[best], 1);
    }
}

__global__ void scan_kernel() {
    int s = 0;
#pragma unroll
    for (int e = 0; e < EE; e++) { g_off[e] = s; s += g_counts[e]; }
    g_off[EE] = s;
}

// gather tokens expert-contiguous, splitting fp32 -> bf16 hi + bf16 lo
__global__ void gather_split_kernel(const float* __restrict__ x) {
    int token = blockIdx.x;
    int dst = g_off[g_expert[token]] + g_pos[token];
    if (threadIdx.x == 0) g_perm[dst] = token;
    const float4* s = (const float4*)(x + (size_t)token * DD);
    uint2* dh = (uint2*)(g_Xh + (size_t)dst * DD);
    uint2* dl = (uint2*)(g_Xl + (size_t)dst * DD);
    for (int i = threadIdx.x; i < DD / 4; i += blockDim.x) {
        float4 v = s[i];
        __nv_bfloat162 h0, h1, l0, l1;
        h0.x = __float2bfloat16(v.x); h0.y = __float2bfloat16(v.y);
        h1.x = __float2bfloat16(v.z); h1.y = __float2bfloat16(v.w);
        l0.x = __float2bfloat16(v.x - __bfloat162float(h0.x));
        l0.y = __float2bfloat16(v.y - __bfloat162float(h0.y));
        l1.x = __float2bfloat16(v.z - __bfloat162float(h1.x));
        l1.y = __float2bfloat16(v.w - __bfloat162float(h1.y));
        uint2 ph, pl;
        ph.x = *(uint32_t*)&h0; ph.y = *(uint32_t*)&h1;
        pl.x = *(uint32_t*)&l0; pl.y = *(uint32_t*)&l1;
        dh[i] = ph; dl[i] = pl;
    }
}

// transpose + split: W [E][KD][ND] fp32 -> T [E][ND][KD] bf16 hi/lo
template <int KD, int ND>
__global__ void wsplit_kernel(const float* __restrict__ W,
                              __nv_bfloat16* __restrict__ Th,
                              __nv_bfloat16* __restrict__ Tl) {
    __shared__ float t[32][33];
    int e = blockIdx.z;
    int k0 = blockIdx.y * 32, n0 = blockIdx.x * 32;
    int tx = threadIdx.x, ty = threadIdx.y;
    const float* Wp = W + (size_t)e * KD * ND;
#pragma unroll
    for (int r = ty; r < 32; r += 8) t[r][tx] = Wp[(size_t)(k0 + r) * ND + n0 + tx];
    __syncthreads();
    size_t ob = (size_t)e * ND * KD;
#pragma unroll
    for (int r = ty; r < 32; r += 8) {
        float v = t[tx][r];
        __nv_bfloat16 h = __float2bfloat16(v);
        __nv_bfloat16 l = __float2bfloat16(v - __bfloat162float(h));
        size_t idx = ob + (size_t)(n0 + r) * KD + k0 + tx;
        Th[idx] = h; Tl[idx] = l;
    }
}

// ---------------- grouped bf16 split-precision HMMA GEMM ----------------
// Block tile 128(M) x 256(N), BK=64. 8 warps in 2(M) x 4(N), each warp 64x64.
// Smem rows are 128 B (64 bf16) with XOR-16B swizzle for conflict-free ldmatrix.
// 3 passes accumulate in fp32 regs: Ah*Bh, Ah*Bl, Al*Bh.
static constexpr int BM = 128, BN = 256, BK = 64;
static constexpr int A_BYTES = BM * 128;           // 16 KB
static constexpr int B_BYTES = BN * 128;           // 32 KB
static constexpr int SMEM_GEMM = 2 * (A_BYTES + B_BYTES);  // 96 KB

template <int K, int NOUT, bool FIRST>
__global__ void __launch_bounds__(256, 1) gemm_mma(
    const __nv_bfloat16* __restrict__ Ah, const __nv_bfloat16* __restrict__ Al,
    const __nv_bfloat16* __restrict__ Bh_all, const __nv_bfloat16* __restrict__ Bl_all,
    const float* __restrict__ ball,
    __nv_bfloat16* __restrict__ OutH, __nv_bfloat16* __restrict__ OutL,
    float* __restrict__ OutF)
{
    constexpr int KC = K / BK;       // chunks per pass (16 or 32, pow2)
    constexpr int NC = 3 * KC;

    int e = blockIdx.z;
    int rowBeg = g_off[e], rowEnd = g_off[e + 1];
    int row0 = rowBeg + blockIdx.y * BM;
    if (row0 >= rowEnd) return;
    int n0 = blockIdx.x * BN;

    const __nv_bfloat16* BhE = Bh_all + (size_t)e * NOUT * K;
    const __nv_bfloat16* BlE = Bl_all + (size_t)e * NOUT * K;
    const float* bias = ball + (size_t)e * NOUT;

    extern __shared__ __align__(128) char smem[];
    uint32_t sb = smem_u32(smem);
    uint32_t aBuf[2] = { sb,               sb + A_BYTES };
    uint32_t bBuf[2] = { sb + 2 * A_BYTES, sb + 2 * A_BYTES + B_BYTES };

    int tid = threadIdx.x;
    int wid = tid >> 5, lane = tid & 31;
    int warpM = wid & 1, warpN = wid >> 1;

    // ---- per-thread gmem->smem geometry (chunk-invariant) ----
    // 3072 16B-chunks per BK-chunk: ids [0,1024) -> A, [1024,3072) -> B
    uint32_t smoA[4], smoB[8];
    int rkA[4], rkB[8];
#pragma unroll
    for (int j = 0; j < 4; j++) {
        int id = tid + j * 256;
        int r = id >> 3, c = id & 7;
        smoA[j] = (uint32_t)(r * 128 + ((c ^ (r & 7)) << 4));
        rkA[j] = r * K + c * 8;
    }
#pragma unroll
    for (int j = 0; j < 8; j++) {
        int id = tid + j * 256;          // 0..2047
        int r = id >> 3, c = id & 7;
        smoB[j] = (uint32_t)(r * 128 + ((c ^ (r & 7)) << 4));
        rkB[j] = r * K + c * 8;
    }

    // ---- ldmatrix per-thread geometry ----
    int rA  = warpM * 64 + (lane & 15);        // A row within tile (for frag)
    int cxA = lane >> 4;                        // A k-half selector
    int sAx = rA & 7;
    int nrl = warpN * 64 + ((lane >> 4) << 3) + (lane & 7);  // B row base
    int kbB = (lane >> 3) & 1;
    int sBx = nrl & 7;

    float acc[4][8][4];
#pragma unroll
    for (int i = 0; i < 4; i++)
#pragma unroll
        for (int j = 0; j < 8; j++)
#pragma unroll
            for (int q = 0; q < 4; q++) acc[i][j][q] = 0.f;

    size_t aRowOff = (size_t)row0 * K;
    size_t bRowOff = (size_t)n0 * K;

    auto issue = [&](int cn) {
        int p = cn / KC;
        int kk = (cn & (KC - 1)) * BK;
        const __nv_bfloat16* Ap = ((p < 2) ? Ah : Al) + aRowOff + kk;
        const __nv_bfloat16* Bp = ((p == 1) ? BlE : BhE) + bRowOff + kk;
        uint32_t ad = aBuf[cn & 1], bd = bBuf[cn & 1];
#pragma unroll
        for (int j = 0; j < 4; j++) cp16(ad + smoA[j], Ap + rkA[j]);
#pragma unroll
        for (int j = 0; j < 8; j++) cp16(bd + smoB[j], Bp + rkB[j]);
        cp_commit();
    };

    issue(0);

    for (int c = 0; c < NC; c++) {
        if (c + 1 < NC) { issue(c + 1); cp_wait1(); }
        else            { cp_wait0(); }
        __syncthreads();
        uint32_t aSm = aBuf[c & 1], bSm = bBuf[c & 1];
#pragma unroll
        for (int ks = 0; ks < 4; ks++) {
            uint32_t afr[4][4];
#pragma unroll
            for (int i = 0; i < 4; i++) {
                uint32_t addr = aSm + (uint32_t)((rA + i * 16) * 128)
                              + (uint32_t)((((ks << 1) + cxA) ^ sAx) << 4);
                LDSM4(afr[i][0], afr[i][1], afr[i][2], afr[i][3], addr);
            }
            uint32_t bfr[4][4];
#pragma unroll
            for (int j = 0; j < 4; j++) {
                uint32_t addr = bSm + (uint32_t)((nrl + j * 16) * 128)
                              + (uint32_t)((((ks << 1) + kbB) ^ sBx) << 4);
                LDSM4(bfr[j][0], bfr[j][1], bfr[j][2], bfr[j][3], addr);
            }
#pragma unroll
            for (int i = 0; i < 4; i++)
#pragma unroll
                for (int j = 0; j < 4; j++) {
                    MMA16816(acc[i][2 * j],     afr[i], bfr[j][0], bfr[j][1]);
                    MMA16816(acc[i][2 * j + 1], afr[i], bfr[j][2], bfr[j][3]);
                }
        }
        __syncthreads();
    }

    // ---- epilogue ----
    int mb = row0 + warpM * 64;
    int nb = n0 + warpN * 64;
    int lr = lane >> 2, lc = (lane & 3) * 2;
#pragma unroll
    for (int i = 0; i < 4; i++) {
#pragma unroll
        for (int h = 0; h < 2; h++) {
            int row = mb + i * 16 + lr + h * 8;
            if (row < rowEnd) {
                if (FIRST) {
                    uint32_t* dh = (uint32_t*)(OutH + (size_t)row * NOUT);
                    uint32_t* dl = (uint32_t*)(OutL + (size_t)row * NOUT);
#pragma unroll
                    for (int j = 0; j < 8; j++) {
                        int col = nb + j * 8 + lc;
                        float v0 = acc[i][j][2 * h]     + __ldg(bias + col);
                        float v1 = acc[i][j][2 * h + 1] + __ldg(bias + col + 1);
                        v0 = fmaxf(v0, 0.f); v1 = fmaxf(v1, 0.f);
                        __nv_bfloat162 hh, ll;
                        hh.x = __float2bfloat16(v0); hh.y = __float2bfloat16(v1);
                        ll.x = __float2bfloat16(v0 - __bfloat162float(hh.x));
                        ll.y = __float2bfloat16(v1 - __bfloat162float(hh.y));
                        dh[col >> 1] = *(uint32_t*)&hh;
                        dl[col >> 1] = *(uint32_t*)&ll;
                    }
                } else {
                    int tok = g_perm[row];
                    float p = g_prob[tok];
                    float2* dst = (float2*)(OutF + (size_t)tok * NOUT);
#pragma unroll
                    for (int j = 0; j < 8; j++) {
                        int col = nb + j * 8 + lc;
                        float2 o;
                        o.x = (acc[i][j][2 * h]     + __ldg(bias + col))     * p;
                        o.y = (acc[i][j][2 * h + 1] + __ldg(bias + col + 1)) * p;
                        dst[col >> 1] = o;
                    }
                }
            }
        }
    }
}

// ---------------- entry ----------------
extern "C" void kernel_launch(void* const* d_in, const int* in_sizes, int n_in,
                              void* d_out, int out_size) {
    const float* x  = (const float*)d_in[0];
    const float* Wr = (const float*)d_in[1];
    const float* br = (const float*)d_in[2];
    const float* W1 = (const float*)d_in[3];
    const float* b1 = (const float*)d_in[4];
    const float* W2 = (const float*)d_in[5];
    const float* b2 = (const float*)d_in[6];
    float* out = (float*)d_out;

    __nv_bfloat16 *Xh, *Xl, *Hh, *Hl, *W1h, *W1l, *W2h, *W2l;
    cudaGetSymbolAddress((void**)&Xh, g_Xh);   cudaGetSymbolAddress((void**)&Xl, g_Xl);
    cudaGetSymbolAddress((void**)&Hh, g_Hh);   cudaGetSymbolAddress((void**)&Hl, g_Hl);
    cudaGetSymbolAddress((void**)&W1h, g_W1h); cudaGetSymbolAddress((void**)&W1l, g_W1l);
    cudaGetSymbolAddress((void**)&W2h, g_W2h); cudaGetSymbolAddress((void**)&W2l, g_W2l);

    cudaFuncSetAttribute(gemm_mma<DD, HH, true>,  cudaFuncAttributeMaxDynamicSharedMemorySize, SMEM_GEMM);
    cudaFuncSetAttribute(gemm_mma<HH, DD, false>, cudaFuncAttributeMaxDynamicSharedMemorySize, SMEM_GEMM);

    zero_counts_kernel<<<1, 32>>>();
    router_kernel<<<TT / 8, 256>>>(x, Wr, br);
    scan_kernel<<<1, 1>>>();
    gather_split_kernel<<<TT, 256>>>(x);

    dim3 tb(32, 8);
    wsplit_kernel<DD, HH><<<dim3(HH / 32, DD / 32, EE), tb>>>(W1, W1h, W1l);
    wsplit_kernel<HH, DD><<<dim3(DD / 32, HH / 32, EE), tb>>>(W2, W2h, W2l);

    dim3 g1(HH / BN, TT / BM, EE);
    gemm_mma<DD, HH, true><<<g1, 256, SMEM_GEMM>>>(Xh, Xl, W1h, W1l, b1, Hh, Hl, nullptr);
    dim3 g2(DD / BN, TT / BM, EE);
    gemm_mma<HH, DD, false><<<g2, 256, SMEM_GEMM>>>(Hh, Hl, W2h, W2l, b2, nullptr, nullptr, out);
}

// round 4
// speedup vs baseline: 2.7373x; 1.1776x over previous
#include <cuda_runtime.h>
#include <cuda_bf16.h>
#include <math.h>
#include <stdint.h>

#define TT 8192
#define DD 1024
#define HH 2048
#define EE 8
#define PAD 256   // row padding so out-of-segment tile rows stay in-bounds

// ---------------- scratch (device globals: allocation-free) ----------------
__device__ int   g_expert[TT];
__device__ int   g_pos[TT];
__device__ float g_prob[TT];
__device__ int   g_counts[EE];
__device__ int   g_off[EE + 1];
__device__ int   g_perm[TT];

__device__ __nv_bfloat16 g_Xh[(TT + PAD) * DD];
__device__ __nv_bfloat16 g_Xl[(TT + PAD) * DD];
__device__ __nv_bfloat16 g_Hh[(TT + PAD) * HH];
__device__ __nv_bfloat16 g_Hl[(TT + PAD) * HH];
__device__ __nv_bfloat16 g_W1h[EE * HH * DD];  // W1^T: [E][H][D]
__device__ __nv_bfloat16 g_W1l[EE * HH * DD];
__device__ __nv_bfloat16 g_W2h[EE * DD * HH];  // W2^T: [E][D][H]
__device__ __nv_bfloat16 g_W2l[EE * DD * HH];

// ---------------- PTX helpers (plain compute_103-safe: sm_80-era ops only) ----
__device__ __forceinline__ uint32_t smem_u32(const void* p) {
    uint32_t a;
    asm("{ .reg .u64 t; cvta.to.shared.u64 t, %1; cvt.u32.u64 %0, t; }" : "=r"(a) : "l"(p));
    return a;
}
__device__ __forceinline__ void cp16(uint32_t dst, const void* src) {
    asm volatile("cp.async.cg.shared.global [%0], [%1], 16;" :: "r"(dst), "l"(src) : "memory");
}
__device__ __forceinline__ void cp_commit() { asm volatile("cp.async.commit_group;" ::: "memory"); }
__device__ __forceinline__ void cp_wait0()  { asm volatile("cp.async.wait_group 0;" ::: "memory"); }
__device__ __forceinline__ void cp_wait1()  { asm volatile("cp.async.wait_group 1;" ::: "memory"); }

#define LDSM4(r0, r1, r2, r3, addr) \
    asm volatile("ldmatrix.sync.aligned.m8n8.x4.shared.b16 {%0,%1,%2,%3}, [%4];" \
        : "=r"(r0), "=r"(r1), "=r"(r2), "=r"(r3) : "r"(addr))

#define MMA16816(d, a, b0v, b1v) \
    asm volatile("mma.sync.aligned.m16n8k16.row.col.f32.bf16.bf16.f32 " \
        "{%0,%1,%2,%3}, {%4,%5,%6,%7}, {%8,%9}, {%0,%1,%2,%3};" \
        : "+f"((d)[0]), "+f"((d)[1]), "+f"((d)[2]), "+f"((d)[3]) \
        : "r"((a)[0]), "r"((a)[1]), "r"((a)[2]), "r"((a)[3]), "r"(b0v), "r"(b1v))

// ---------------- tiny setup kernels ----------------
__global__ void zero_counts_kernel() {
    if (threadIdx.x < EE) g_counts[threadIdx.x] = 0;
}

// fp32 router: 1 warp per token (exact, so argmax matches reference)
__global__ void router_kernel(const float* __restrict__ x,
                              const float* __restrict__ Wr,
                              const float* __restrict__ br) {
    int token = blockIdx.x * 8 + (threadIdx.x >> 5);
    int lane  = threadIdx.x & 31;
    const float* xr = x + (size_t)token * DD;
    float acc[EE];
#pragma unroll
    for (int e = 0; e < EE; e++) acc[e] = 0.f;
    for (int d = lane; d < DD; d += 32) {
        float xv = xr[d];
        const float4* w = (const float4*)(Wr + d * EE);
        float4 w0 = w[0], w1 = w[1];
        acc[0] += xv * w0.x; acc[1] += xv * w0.y;
        acc[2] += xv * w0.z; acc[3] += xv * w0.w;
        acc[4] += xv * w1.x; acc[5] += xv * w1.y;
        acc[6] += xv * w1.z; acc[7] += xv * w1.w;
    }
#pragma unroll
    for (int e = 0; e < EE; e++) {
#pragma unroll
        for (int o = 16; o; o >>= 1) acc[e] += __shfl_xor_sync(0xffffffffu, acc[e], o);
    }
    if (lane == 0) {
        float m = -1e30f; int best = 0;
#pragma unroll
        for (int e = 0; e < EE; e++) {
            float l = acc[e] + br[e];
            acc[e] = l;
            if (l > m) { m = l; best = e; }
        }
        float s = 0.f;
#pragma unroll
        for (int e = 0; e < EE; e++) s += expf(acc[e] - m);
        g_expert[token] = best;
        g_prob[token]   = 1.f / s;
        g_pos[token]    = atomicAdd(&g_counts[best], 1);
    }
}

__global__ void scan_kernel() {
    int s = 0;
#pragma unroll
    for (int e = 0; e < EE; e++) { g_off[e] = s; s += g_counts[e]; }
    g_off[EE] = s;
}

// gather tokens expert-contiguous, splitting fp32 -> bf16 hi + bf16 lo
__global__ void gather_split_kernel(const float* __restrict__ x) {
    int token = blockIdx.x;
    int dst = g_off[g_expert[token]] + g_pos[token];
    if (threadIdx.x == 0) g_perm[dst] = token;
    const float4* s = (const float4*)(x + (size_t)token * DD);
    uint2* dh = (uint2*)(g_Xh + (size_t)dst * DD);
    uint2* dl = (uint2*)(g_Xl + (size_t)dst * DD);
    for (int i = threadIdx.x; i < DD / 4; i += blockDim.x) {
        float4 v = s[i];
        __nv_bfloat162 h0, h1, l0, l1;
        h0.x = __float2bfloat16(v.x); h0.y = __float2bfloat16(v.y);
        h1.x = __float2bfloat16(v.z); h1.y = __float2bfloat16(v.w);
        l0.x = __float2bfloat16(v.x - __bfloat162float(h0.x));
        l0.y = __float2bfloat16(v.y - __bfloat162float(h0.y));
        l1.x = __float2bfloat16(v.z - __bfloat162float(h1.x));
        l1.y = __float2bfloat16(v.w - __bfloat162float(h1.y));
        uint2 ph, pl;
        ph.x = *(uint32_t*)&h0; ph.y = *(uint32_t*)&h1;
        pl.x = *(uint32_t*)&l0; pl.y = *(uint32_t*)&l1;
        dh[i] = ph; dl[i] = pl;
    }
}

// transpose + split: W [E][KD][ND] fp32 -> T [E][ND][KD] bf16 hi/lo
template <int KD, int ND>
__global__ void wsplit_kernel(const float* __restrict__ W,
                              __nv_bfloat16* __restrict__ Th,
                              __nv_bfloat16* __restrict__ Tl) {
    __shared__ float t[32][33];
    int e = blockIdx.z;
    int k0 = blockIdx.y * 32, n0 = blockIdx.x * 32;
    int tx = threadIdx.x, ty = threadIdx.y;
    const float* Wp = W + (size_t)e * KD * ND;
#pragma unroll
    for (int r = ty; r < 32; r += 8) t[r][tx] = Wp[(size_t)(k0 + r) * ND + n0 + tx];
    __syncthreads();
    size_t ob = (size_t)e * ND * KD;
#pragma unroll
    for (int r = ty; r < 32; r += 8) {
        float v = t[tx][r];
        __nv_bfloat16 h = __float2bfloat16(v);
        __nv_bfloat16 l = __float2bfloat16(v - __bfloat162float(h));
        size_t idx = ob + (size_t)(n0 + r) * KD + k0 + tx;
        Th[idx] = h; Tl[idx] = l;
    }
}

// ---------------- grouped bf16 split-precision HMMA GEMM (fused 3-product) ----
// Block tile 128(M) x 256(N), BK=64. 8 warps in 2(M) x 4(N), each warp 64x64.
// Per k-chunk, all four tiles {Ah, Al, Bh, Bl} are staged once; A fragments are
// held in registers and reused against Bh then Bl:
//   acc += Ah*Bh + Al*Bh + Ah*Bl     (lo*lo dropped, ~2^-18)
// Single K-loop (no 3 passes) -> 33% less gmem, 50% less ldmatrix traffic.
static constexpr int BM = 128, BN = 256, BK = 64;
static constexpr int A_T = BM * 128;                    // 16 KB per A tile
static constexpr int B_T = BN * 128;                    // 32 KB per B tile
static constexpr int STAGE = 2 * A_T + 2 * B_T;         // 96 KB
static constexpr int SMEM_GEMM = 2 * STAGE;             // 192 KB (<227 KB cap)

template <int K, int NOUT, bool FIRST>
__global__ void __launch_bounds__(256, 1) gemm_mma(
    const __nv_bfloat16* __restrict__ Ah, const __nv_bfloat16* __restrict__ Al,
    const __nv_bfloat16* __restrict__ Bh_all, const __nv_bfloat16* __restrict__ Bl_all,
    const float* __restrict__ ball,
    __nv_bfloat16* __restrict__ OutH, __nv_bfloat16* __restrict__ OutL,
    float* __restrict__ OutF)
{
    constexpr int KC = K / BK;

    int e = blockIdx.z;
    int rowBeg = g_off[e], rowEnd = g_off[e + 1];
    int row0 = rowBeg + blockIdx.y * BM;
    if (row0 >= rowEnd) return;
    int n0 = blockIdx.x * BN;

    const __nv_bfloat16* BhE = Bh_all + (size_t)e * NOUT * K;
    const __nv_bfloat16* BlE = Bl_all + (size_t)e * NOUT * K;
    const float* bias = ball + (size_t)e * NOUT;

    extern __shared__ __align__(128) char smem[];
    uint32_t sb = smem_u32(smem);

    int tid = threadIdx.x;
    int wid = tid >> 5, lane = tid & 31;
    int warpM = wid & 1, warpN = wid >> 1;

    // ---- per-thread gmem->smem geometry (chunk-invariant) ----
    uint32_t smoA[4], smoB[8];
    int rkA[4], rkB[8];
#pragma unroll
    for (int j = 0; j < 4; j++) {
        int id = tid + j * 256;
        int r = id >> 3, c = id & 7;
        smoA[j] = (uint32_t)(r * 128 + ((c ^ (r & 7)) << 4));
        rkA[j] = r * K + c * 8;
    }
#pragma unroll
    for (int j = 0; j < 8; j++) {
        int id = tid + j * 256;          // 0..2047
        int r = id >> 3, c = id & 7;
        smoB[j] = (uint32_t)(r * 128 + ((c ^ (r & 7)) << 4));
        rkB[j] = r * K + c * 8;
    }

    // ---- ldmatrix per-thread geometry ----
    int rA  = warpM * 64 + (lane & 15);
    int cxA = lane >> 4;
    int sAx = rA & 7;
    int nrl = warpN * 64 + ((lane >> 4) << 3) + (lane & 7);
    int kbB = (lane >> 3) & 1;
    int sBx = nrl & 7;

    float acc[4][8][4];
#pragma unroll
    for (int i = 0; i < 4; i++)
#pragma unroll
        for (int j = 0; j < 8; j++)
#pragma unroll
            for (int q = 0; q < 4; q++) acc[i][j][q] = 0.f;

    size_t aRowOff = (size_t)row0 * K;
    size_t bRowOff = (size_t)n0 * K;

    auto issue = [&](int cn) {
        int kk = cn * BK;
        uint32_t st = sb + (uint32_t)((cn & 1) * STAGE);
        const __nv_bfloat16* Aph = Ah  + aRowOff + kk;
        const __nv_bfloat16* Apl = Al  + aRowOff + kk;
        const __nv_bfloat16* Bph = BhE + bRowOff + kk;
        const __nv_bfloat16* Bpl = BlE + bRowOff + kk;
#pragma unroll
        for (int j = 0; j < 4; j++) cp16(st + smoA[j], Aph + rkA[j]);
#pragma unroll
        for (int j = 0; j < 4; j++) cp16(st + A_T + smoA[j], Apl + rkA[j]);
#pragma unroll
        for (int j = 0; j < 8; j++) cp16(st + 2 * A_T + smoB[j], Bph + rkB[j]);
#pragma unroll
        for (int j = 0; j < 8; j++) cp16(st + 2 * A_T + B_T + smoB[j], Bpl + rkB[j]);
        cp_commit();
    };

    issue(0);

    for (int c = 0; c < KC; c++) {
        if (c + 1 < KC) { issue(c + 1); cp_wait1(); }
        else            { cp_wait0(); }
        __syncthreads();
        uint32_t st = sb + (uint32_t)((c & 1) * STAGE);
        uint32_t ahSm = st, alSm = st + A_T, bhSm = st + 2 * A_T, blSm = st + 2 * A_T + B_T;
#pragma unroll
        for (int ks = 0; ks < 4; ks++) {
            uint32_t aro = (uint32_t)((((ks << 1) + cxA) ^ sAx) << 4);
            uint32_t bro = (uint32_t)((((ks << 1) + kbB) ^ sBx) << 4);
            uint32_t ahf[4][4], alf[4][4];
#pragma unroll
            for (int i = 0; i < 4; i++) {
                uint32_t roff = (uint32_t)((rA + i * 16) * 128) + aro;
                LDSM4(ahf[i][0], ahf[i][1], ahf[i][2], ahf[i][3], ahSm + roff);
                LDSM4(alf[i][0], alf[i][1], alf[i][2], alf[i][3], alSm + roff);
            }
            {   // Bh: used by both Ah and Al
                uint32_t bf[4][4];
#pragma unroll
                for (int j = 0; j < 4; j++) {
                    uint32_t roff = (uint32_t)((nrl + j * 16) * 128) + bro;
                    LDSM4(bf[j][0], bf[j][1], bf[j][2], bf[j][3], bhSm + roff);
                }
#pragma unroll
                for (int i = 0; i < 4; i++)
#pragma unroll
                    for (int j = 0; j < 4; j++) {
                        MMA16816(acc[i][2 * j],     ahf[i], bf[j][0], bf[j][1]);
                        MMA16816(acc[i][2 * j + 1], ahf[i], bf[j][2], bf[j][3]);
                    }
#pragma unroll
                for (int i = 0; i < 4; i++)
#pragma unroll
                    for (int j = 0; j < 4; j++) {
                        MMA16816(acc[i][2 * j],     alf[i], bf[j][0], bf[j][1]);
                        MMA16816(acc[i][2 * j + 1], alf[i], bf[j][2], bf[j][3]);
                    }
            }
            {   // Bl: used by Ah only
                uint32_t bf[4][4];
#pragma unroll
                for (int j = 0; j < 4; j++) {
                    uint32_t roff = (uint32_t)((nrl + j * 16) * 128) + bro;
                    LDSM4(bf[j][0], bf[j][1], bf[j][2], bf[j][3], blSm + roff);
                }
#pragma unroll
                for (int i = 0; i < 4; i++)
#pragma unroll
                    for (int j = 0; j < 4; j++) {
                        MMA16816(acc[i][2 * j],     ahf[i], bf[j][0], bf[j][1]);
                        MMA16816(acc[i][2 * j + 1], ahf[i], bf[j][2], bf[j][3]);
                    }
            }
        }
        __syncthreads();
    }

    // ---- epilogue ----
    int mb = row0 + warpM * 64;
    int nb = n0 + warpN * 64;
    int lr = lane >> 2, lc = (lane & 3) * 2;
    float2 blv[8];
#pragma unroll
    for (int j = 0; j < 8; j++) {
        int col = nb + j * 8 + lc;
        blv[j].x = __ldg(bias + col);
        blv[j].y = __ldg(bias + col + 1);
    }
#pragma unroll
    for (int i = 0; i < 4; i++) {
#pragma unroll
        for (int h = 0; h < 2; h++) {
            int row = mb + i * 16 + lr + h * 8;
            if (row < rowEnd) {
                if (FIRST) {
                    uint32_t* dh = (uint32_t*)(OutH + (size_t)row * NOUT);
                    uint32_t* dl = (uint32_t*)(OutL + (size_t)row * NOUT);
#pragma unroll
                    for (int j = 0; j < 8; j++) {
                        int col = nb + j * 8 + lc;
                        float v0 = acc[i][j][2 * h]     + blv[j].x;
                        float v1 = acc[i][j][2 * h + 1] + blv[j].y;
                        v0 = fmaxf(v0, 0.f); v1 = fmaxf(v1, 0.f);
                        __nv_bfloat162 hh, ll;
                        hh.x = __float2bfloat16(v0); hh.y = __float2bfloat16(v1);
                        ll.x = __float2bfloat16(v0 - __bfloat162float(hh.x));
                        ll.y = __float2bfloat16(v1 - __bfloat162float(hh.y));
                        dh[col >> 1] = *(uint32_t*)&hh;
                        dl[col >> 1] = *(uint32_t*)&ll;
                    }
                } else {
                    int tok = g_perm[row];
                    float p = g_prob[tok];
                    float2* dst = (float2*)(OutF + (size_t)tok * NOUT);
#pragma unroll
                    for (int j = 0; j < 8; j++) {
                        int col = nb + j * 8 + lc;
                        float2 o;
                        o.x = (acc[i][j][2 * h]     + blv[j].x) * p;
                        o.y = (acc[i][j][2 * h + 1] + blv[j].y) * p;
                        dst[col >> 1] = o;
                    }
                }
            }
        }
    }
}

// ---------------- entry ----------------
extern "C" void kernel_launch(void* const* d_in, const int* in_sizes, int n_in,
                              void* d_out, int out_size) {
    const float* x  = (const float*)d_in[0];
    const float* Wr = (const float*)d_in[1];
    const float* br = (const float*)d_in[2];
    const float* W1 = (const float*)d_in[3];
    const float* b1 = (const float*)d_in[4];
    const float* W2 = (const float*)d_in[5];
    const float* b2 = (const float*)d_in[6];
    float* out = (float*)d_out;

    __nv_bfloat16 *Xh, *Xl, *Hh, *Hl, *W1h, *W1l, *W2h, *W2l;
    cudaGetSymbolAddress((void**)&Xh, g_Xh);   cudaGetSymbolAddress((void**)&Xl, g_Xl);
    cudaGetSymbolAddress((void**)&Hh, g_Hh);   cudaGetSymbolAddress((void**)&Hl, g_Hl);
    cudaGetSymbolAddress((void**)&W1h, g_W1h); cudaGetSymbolAddress((void**)&W1l, g_W1l);
    cudaGetSymbolAddress((void**)&W2h, g_W2h); cudaGetSymbolAddress((void**)&W2l, g_W2l);

    cudaFuncSetAttribute(gemm_mma<DD, HH, true>,  cudaFuncAttributeMaxDynamicSharedMemorySize, SMEM_GEMM);
    cudaFuncSetAttribute(gemm_mma<HH, DD, false>, cudaFuncAttributeMaxDynamicSharedMemorySize, SMEM_GEMM);

    zero_counts_kernel<<<1, 32>>>();
    router_kernel<<<TT / 8, 256>>>(x, Wr, br);
    scan_kernel<<<1, 1>>>();
    gather_split_kernel<<<TT, 256>>>(x);

    dim3 tb(32, 8);
    wsplit_kernel<DD, HH><<<dim3(HH / 32, DD / 32, EE), tb>>>(W1, W1h, W1l);
    wsplit_kernel<HH, DD><<<dim3(DD / 32, HH / 32, EE), tb>>>(W2, W2h, W2l);

    dim3 g1(HH / BN, TT / BM, EE);
    gemm_mma<DD, HH, true><<<g1, 256, SMEM_GEMM>>>(Xh, Xl, W1h, W1l, b1, Hh, Hl, nullptr);
    dim3 g2(DD / BN, TT / BM, EE);
    gemm_mma<HH, DD, false><<<g2, 256, SMEM_GEMM>>>(Hh, Hl, W2h, W2l, b2, nullptr, nullptr, out);
}

// round 5
// speedup vs baseline: 3.7035x; 1.3530x over previous
#include <cuda_runtime.h>
#include <cuda_fp16.h>
#include <math.h>
#include <stdint.h>

#define TT 8192
#define DD 1024
#define HH 2048
#define EE 8
#define PAD 256   // row padding so out-of-segment tile rows stay in-bounds

// ---------------- scratch (device globals: allocation-free) ----------------
__device__ int   g_expert[TT];
__device__ int   g_pos[TT];
__device__ float g_prob[TT];
__device__ int   g_counts[EE];
__device__ int   g_off[EE + 1];
__device__ int   g_perm[TT];

__device__ __half g_Xh[(TT + PAD) * DD];
__device__ __half g_Xl[(TT + PAD) * DD];
__device__ __half g_Hh[(TT + PAD) * HH];
__device__ __half g_Hl[(TT + PAD) * HH];
__device__ __half g_W1h[EE * HH * DD];  // W1^T: [E][H][D], fp16
__device__ __half g_W2h[EE * DD * HH];  // W2^T: [E][D][H], fp16

// ---------------- PTX helpers (plain compute_103-safe: sm_80-era ops only) ----
__device__ __forceinline__ uint32_t smem_u32(const void* p) {
    uint32_t a;
    asm("{ .reg .u64 t; cvta.to.shared.u64 t, %1; cvt.u32.u64 %0, t; }" : "=r"(a) : "l"(p));
    return a;
}
__device__ __forceinline__ void cp16(uint32_t dst, const void* src) {
    asm volatile("cp.async.cg.shared.global [%0], [%1], 16;" :: "r"(dst), "l"(src) : "memory");
}
__device__ __forceinline__ void cp_commit() { asm volatile("cp.async.commit_group;" ::: "memory"); }
__device__ __forceinline__ void cp_wait0()  { asm volatile("cp.async.wait_group 0;" ::: "memory"); }
__device__ __forceinline__ void cp_wait1()  { asm volatile("cp.async.wait_group 1;" ::: "memory"); }

#define LDSM4(r0, r1, r2, r3, addr) \
    asm volatile("ldmatrix.sync.aligned.m8n8.x4.shared.b16 {%0,%1,%2,%3}, [%4];" \
        : "=r"(r0), "=r"(r1), "=r"(r2), "=r"(r3) : "r"(addr))

#define MMA16816(d, a, b0v, b1v) \
    asm volatile("mma.sync.aligned.m16n8k16.row.col.f32.f16.f16.f32 " \
        "{%0,%1,%2,%3}, {%4,%5,%6,%7}, {%8,%9}, {%0,%1,%2,%3};" \
        : "+f"((d)[0]), "+f"((d)[1]), "+f"((d)[2]), "+f"((d)[3]) \
        : "r"((a)[0]), "r"((a)[1]), "r"((a)[2]), "r"((a)[3]), "r"(b0v), "r"(b1v))

// ---------------- tiny setup kernels ----------------
__global__ void zero_counts_kernel() {
    if (threadIdx.x < EE) g_counts[threadIdx.x] = 0;
}

// fp32 router: 1 warp per token (exact, so argmax matches reference)
__global__ void router_kernel(const float* __restrict__ x,
                              const float* __restrict__ Wr,
                              const float* __restrict__ br) {
    int token = blockIdx.x * 8 + (threadIdx.x >> 5);
    int lane  = threadIdx.x & 31;
    const float* xr = x + (size_t)token * DD;
    float acc[EE];
#pragma unroll
    for (int e = 0; e < EE; e++) acc[e] = 0.f;
    for (int d = lane; d < DD; d += 32) {
        float xv = xr[d];
        const float4* w = (const float4*)(Wr + d * EE);
        float4 w0 = w[0], w1 = w[1];
        acc[0] += xv * w0.x; acc[1] += xv * w0.y;
        acc[2] += xv * w0.z; acc[3] += xv * w0.w;
        acc[4] += xv * w1.x; acc[5] += xv * w1.y;
        acc[6] += xv * w1.z; acc[7] += xv * w1.w;
    }
#pragma unroll
    for (int e = 0; e < EE; e++) {
#pragma unroll
        for (int o = 16; o; o >>= 1) acc[e] += __shfl_xor_sync(0xffffffffu, acc[e], o);
    }
    if (lane == 0) {
        float m = -1e30f; int best = 0;
#pragma unroll
        for (int e = 0; e < EE; e++) {
            float l = acc[e] + br[e];
            acc[e] = l;
            if (l > m) { m = l; best = e; }
        }
        float s = 0.f;
#pragma unroll
        for (int e = 0; e < EE; e++) s += expf(acc[e] - m);
        g_expert[token] = best;
        g_prob[token]   = 1.f / s;
        g_pos[token]    = atomicAdd(&g_counts[best], 1);
    }
}

__global__ void scan_kernel() {
    int s = 0;
#pragma unroll
    for (int e = 0; e < EE; e++) { g_off[e] = s; s += g_counts[e]; }
    g_off[EE] = s;
}

// gather tokens expert-contiguous, splitting fp32 -> fp16 hi + fp16 lo
__global__ void gather_split_kernel(const float* __restrict__ x) {
    int token = blockIdx.x;
    int dst = g_off[g_expert[token]] + g_pos[token];
    if (threadIdx.x == 0) g_perm[dst] = token;
    const float4* s = (const float4*)(x + (size_t)token * DD);
    uint2* dh = (uint2*)(g_Xh + (size_t)dst * DD);
    uint2* dl = (uint2*)(g_Xl + (size_t)dst * DD);
    for (int i = threadIdx.x; i < DD / 4; i += blockDim.x) {
        float4 v = s[i];
        __half2 h0, h1, l0, l1;
        h0.x = __float2half_rn(v.x); h0.y = __float2half_rn(v.y);
        h1.x = __float2half_rn(v.z); h1.y = __float2half_rn(v.w);
        l0.x = __float2half_rn(v.x - __half2float(h0.x));
        l0.y = __float2half_rn(v.y - __half2float(h0.y));
        l1.x = __float2half_rn(v.z - __half2float(h1.x));
        l1.y = __float2half_rn(v.w - __half2float(h1.y));
        uint2 ph, pl;
        ph.x = *(uint32_t*)&h0; ph.y = *(uint32_t*)&h1;
        pl.x = *(uint32_t*)&l0; pl.y = *(uint32_t*)&l1;
        dh[i] = ph; dl[i] = pl;
    }
}

// transpose: W [E][KD][ND] fp32 -> T [E][ND][KD] fp16 (single, round-to-nearest)
template <int KD, int ND>
__global__ void wsplit_kernel(const float* __restrict__ W,
                              __half* __restrict__ Th) {
    __shared__ float t[32][33];
    int e = blockIdx.z;
    int k0 = blockIdx.y * 32, n0 = blockIdx.x * 32;
    int tx = threadIdx.x, ty = threadIdx.y;
    const float* Wp = W + (size_t)e * KD * ND;
#pragma unroll
    for (int r = ty; r < 32; r += 8) t[r][tx] = Wp[(size_t)(k0 + r) * ND + n0 + tx];
    __syncthreads();
    size_t ob = (size_t)e * ND * KD;
#pragma unroll
    for (int r = ty; r < 32; r += 8) {
        Th[ob + (size_t)(n0 + r) * KD + k0 + tx] = __float2half_rn(t[tx][r]);
    }
}

// ---------------- grouped fp16 split-A HMMA GEMM (2-product) ----------------
// Block tile 128(M) x 256(N), BK=64. 8 warps in 2(M) x 4(N), each warp 64x64.
// Per k-chunk, stage {Ah, Al, Bh}; A fragments held in regs, B loaded once:
//   acc += Ah*Bh + Al*Bh  == (A exact to 22 bits) * fp16(B)
static constexpr int BM = 128, BN = 256, BK = 64;
static constexpr int A_T = BM * 128;                    // 16 KB per A tile
static constexpr int B_T = BN * 128;                    // 32 KB B tile
static constexpr int STAGE = 2 * A_T + B_T;             // 64 KB
static constexpr int SMEM_GEMM = 2 * STAGE;             // 128 KB

template <int K, int NOUT, bool FIRST>
__global__ void __launch_bounds__(256, 1) gemm_mma(
    const __half* __restrict__ Ah, const __half* __restrict__ Al,
    const __half* __restrict__ Bh_all,
    const float* __restrict__ ball,
    __half* __restrict__ OutH, __half* __restrict__ OutL,
    float* __restrict__ OutF)
{
    constexpr int KC = K / BK;

    int e = blockIdx.z;
    int rowBeg = g_off[e], rowEnd = g_off[e + 1];
    int row0 = rowBeg + blockIdx.y * BM;
    if (row0 >= rowEnd) return;
    int n0 = blockIdx.x * BN;

    const __half* BhE = Bh_all + (size_t)e * NOUT * K;
    const float* bias = ball + (size_t)e * NOUT;

    extern __shared__ __align__(128) char smem[];
    uint32_t sb = smem_u32(smem);

    int tid = threadIdx.x;
    int wid = tid >> 5, lane = tid & 31;
    int warpM = wid & 1, warpN = wid >> 1;

    // ---- per-thread gmem->smem geometry (chunk-invariant) ----
    uint32_t smoA[4], smoB[8];
    int rkA[4], rkB[8];
#pragma unroll
    for (int j = 0; j < 4; j++) {
        int id = tid + j * 256;
        int r = id >> 3, c = id & 7;
        smoA[j] = (uint32_t)(r * 128 + ((c ^ (r & 7)) << 4));
        rkA[j] = r * K + c * 8;
    }
#pragma unroll
    for (int j = 0; j < 8; j++) {
        int id = tid + j * 256;          // 0..2047
        int r = id >> 3, c = id & 7;
        smoB[j] = (uint32_t)(r * 128 + ((c ^ (r & 7)) << 4));
        rkB[j] = r * K + c * 8;
    }

    // ---- ldmatrix per-thread geometry ----
    int rA  = warpM * 64 + (lane & 15);
    int cxA = lane >> 4;
    int sAx = rA & 7;
    int nrl = warpN * 64 + ((lane >> 4) << 3) + (lane & 7);
    int kbB = (lane >> 3) & 1;
    int sBx = nrl & 7;

    float acc[4][8][4];
#pragma unroll
    for (int i = 0; i < 4; i++)
#pragma unroll
        for (int j = 0; j < 8; j++)
#pragma unroll
            for (int q = 0; q < 4; q++) acc[i][j][q] = 0.f;

    size_t aRowOff = (size_t)row0 * K;
    size_t bRowOff = (size_t)n0 * K;

    auto issue = [&](int cn) {
        int kk = cn * BK;
        uint32_t st = sb + (uint32_t)((cn & 1) * STAGE);
        const __half* Aph = Ah  + aRowOff + kk;
        const __half* Apl = Al  + aRowOff + kk;
        const __half* Bph = BhE + bRowOff + kk;
#pragma unroll
        for (int j = 0; j < 4; j++) cp16(st + smoA[j], Aph + rkA[j]);
#pragma unroll
        for (int j = 0; j < 4; j++) cp16(st + A_T + smoA[j], Apl + rkA[j]);
#pragma unroll
        for (int j = 0; j < 8; j++) cp16(st + 2 * A_T + smoB[j], Bph + rkB[j]);
        cp_commit();
    };

    issue(0);

    for (int c = 0; c < KC; c++) {
        if (c + 1 < KC) { issue(c + 1); cp_wait1(); }
        else            { cp_wait0(); }
        __syncthreads();
        uint32_t st = sb + (uint32_t)((c & 1) * STAGE);
        uint32_t ahSm = st, alSm = st + A_T, bhSm = st + 2 * A_T;
#pragma unroll
        for (int ks = 0; ks < 4; ks++) {
            uint32_t aro = (uint32_t)((((ks << 1) + cxA) ^ sAx) << 4);
            uint32_t bro = (uint32_t)((((ks << 1) + kbB) ^ sBx) << 4);
            uint32_t ahf[4][4], alf[4][4];
#pragma unroll
            for (int i = 0; i < 4; i++) {
                uint32_t roff = (uint32_t)((rA + i * 16) * 128) + aro;
                LDSM4(ahf[i][0], ahf[i][1], ahf[i][2], ahf[i][3], ahSm + roff);
                LDSM4(alf[i][0], alf[i][1], alf[i][2], alf[i][3], alSm + roff);
            }
            uint32_t bf[4][4];
#pragma unroll
            for (int j = 0; j < 4; j++) {
                uint32_t roff = (uint32_t)((nrl + j * 16) * 128) + bro;
                LDSM4(bf[j][0], bf[j][1], bf[j][2], bf[j][3], bhSm + roff);
            }
#pragma unroll
            for (int i = 0; i < 4; i++)
#pragma unroll
                for (int j = 0; j < 4; j++) {
                    MMA16816(acc[i][2 * j],     ahf[i], bf[j][0], bf[j][1]);
                    MMA16816(acc[i][2 * j + 1], ahf[i], bf[j][2], bf[j][3]);
                }
#pragma unroll
            for (int i = 0; i < 4; i++)
#pragma unroll
                for (int j = 0; j < 4; j++) {
                    MMA16816(acc[i][2 * j],     alf[i], bf[j][0], bf[j][1]);
                    MMA16816(acc[i][2 * j + 1], alf[i], bf[j][2], bf[j][3]);
                }
        }
        __syncthreads();
    }

    // ---- epilogue ----
    int mb = row0 + warpM * 64;
    int nb = n0 + warpN * 64;
    int lr = lane >> 2, lc = (lane & 3) * 2;
    float2 blv[8];
#pragma unroll
    for (int j = 0; j < 8; j++) {
        int col = nb + j * 8 + lc;
        blv[j].x = __ldg(bias + col);
        blv[j].y = __ldg(bias + col + 1);
    }
#pragma unroll
    for (int i = 0; i < 4; i++) {
#pragma unroll
        for (int h = 0; h < 2; h++) {
            int row = mb + i * 16 + lr + h * 8;
            if (row < rowEnd) {
                if (FIRST) {
                    uint32_t* dh = (uint32_t*)(OutH + (size_t)row * NOUT);
                    uint32_t* dl = (uint32_t*)(OutL + (size_t)row * NOUT);
#pragma unroll
                    for (int j = 0; j < 8; j++) {
                        int col = nb + j * 8 + lc;
                        float v0 = acc[i][j][2 * h]     + blv[j].x;
                        float v1 = acc[i][j][2 * h + 1] + blv[j].y;
                        v0 = fmaxf(v0, 0.f); v1 = fmaxf(v1, 0.f);
                        __half2 hh, ll;
                        hh.x = __float2half_rn(v0); hh.y = __float2half_rn(v1);
                        ll.x = __float2half_rn(v0 - __half2float(hh.x));
                        ll.y = __float2half_rn(v1 - __half2float(hh.y));
                        dh[col >> 1] = *(uint32_t*)&hh;
                        dl[col >> 1] = *(uint32_t*)&ll;
                    }
                } else {
                    int tok = g_perm[row];
                    float p = g_prob[tok];
                    float2* dst = (float2*)(OutF + (size_t)tok * NOUT);
#pragma unroll
                    for (int j = 0; j < 8; j++) {
                        int col = nb + j * 8 + lc;
                        float2 o;
                        o.x = (acc[i][j][2 * h]     + blv[j].x) * p;
                        o.y = (acc[i][j][2 * h + 1] + blv[j].y) * p;
                        dst[col >> 1] = o;
                    }
                }
            }
        }
    }
}

// ---------------- entry ----------------
extern "C" void kernel_launch(void* const* d_in, const int* in_sizes, int n_in,
                              void* d_out, int out_size) {
    const float* x  = (const float*)d_in[0];
    const float* Wr = (const float*)d_in[1];
    const float* br = (const float*)d_in[2];
    const float* W1 = (const float*)d_in[3];
    const float* b1 = (const float*)d_in[4];
    const float* W2 = (const float*)d_in[5];
    const float* b2 = (const float*)d_in[6];
    float* out = (float*)d_out;

    __half *Xh, *Xl, *Hh, *Hl, *W1h, *W2h;
    cudaGetSymbolAddress((void**)&Xh, g_Xh);   cudaGetSymbolAddress((void**)&Xl, g_Xl);
    cudaGetSymbolAddress((void**)&Hh, g_Hh);   cudaGetSymbolAddress((void**)&Hl, g_Hl);
    cudaGetSymbolAddress((void**)&W1h, g_W1h); cudaGetSymbolAddress((void**)&W2h, g_W2h);

    cudaFuncSetAttribute(gemm_mma<DD, HH, true>,  cudaFuncAttributeMaxDynamicSharedMemorySize, SMEM_GEMM);
    cudaFuncSetAttribute(gemm_mma<HH, DD, false>, cudaFuncAttributeMaxDynamicSharedMemorySize, SMEM_GEMM);

    zero_counts_kernel<<<1, 32>>>();
    router_kernel<<<TT / 8, 256>>>(x, Wr, br);
    scan_kernel<<<1, 1>>>();
    gather_split_kernel<<<TT, 256>>>(x);

    dim3 tb(32, 8);
    wsplit_kernel<DD, HH><<<dim3(HH / 32, DD / 32, EE), tb>>>(W1, W1h);
    wsplit_kernel<HH, DD><<<dim3(DD / 32, HH / 32, EE), tb>>>(W2, W2h);

    dim3 g1(HH / BN, TT / BM, EE);
    gemm_mma<DD, HH, true><<<g1, 256, SMEM_GEMM>>>(Xh, Xl, W1h, b1, Hh, Hl, nullptr);
    dim3 g2(DD / BN, TT / BM, EE);
    gemm_mma<HH, DD, false><<<g2, 256, SMEM_GEMM>>>(Hh, Hl, W2h, b2, nullptr, nullptr, out);
}

// round 6
// speedup vs baseline: 5.5847x; 1.5079x over previous
#include <cuda_runtime.h>
#include <cuda_fp16.h>
#include <math.h>
#include <stdint.h>

#define TT 8192
#define DD 1024
#define HH 2048
#define EE 8
#define PAD 256   // row padding so out-of-segment tile rows stay in-bounds

// ---------------- scratch (device globals: allocation-free) ----------------
__device__ int   g_expert[TT];
__device__ int   g_pos[TT];
__device__ float g_prob[TT];
__device__ int   g_counts[EE];
__device__ int   g_off[EE + 1];
__device__ int   g_perm[TT];

__device__ __half g_Xh[(TT + PAD) * DD];
__device__ __half g_Hh[(TT + PAD) * HH];
__device__ __half g_W1h[EE * HH * DD];  // W1^T: [E][H][D], fp16
__device__ __half g_W2h[EE * DD * HH];  // W2^T: [E][D][H], fp16

// ---------------- PTX helpers (plain compute_103-safe: sm_80-era ops only) ----
__device__ __forceinline__ uint32_t smem_u32(const void* p) {
    uint32_t a;
    asm("{ .reg .u64 t; cvta.to.shared.u64 t, %1; cvt.u32.u64 %0, t; }" : "=r"(a) : "l"(p));
    return a;
}
__device__ __forceinline__ void cp16(uint32_t dst, const void* src) {
    asm volatile("cp.async.cg.shared.global [%0], [%1], 16;" :: "r"(dst), "l"(src) : "memory");
}
__device__ __forceinline__ void cp_commit() { asm volatile("cp.async.commit_group;" ::: "memory"); }
__device__ __forceinline__ void cp_wait2()  { asm volatile("cp.async.wait_group 2;" ::: "memory"); }

#define LDSM4(r0, r1, r2, r3, addr) \
    asm volatile("ldmatrix.sync.aligned.m8n8.x4.shared.b16 {%0,%1,%2,%3}, [%4];" \
        : "=r"(r0), "=r"(r1), "=r"(r2), "=r"(r3) : "r"(addr))

#define MMA16816(d, a, b0v, b1v) \
    asm volatile("mma.sync.aligned.m16n8k16.row.col.f32.f16.f16.f32 " \
        "{%0,%1,%2,%3}, {%4,%5,%6,%7}, {%8,%9}, {%0,%1,%2,%3};" \
        : "+f"((d)[0]), "+f"((d)[1]), "+f"((d)[2]), "+f"((d)[3]) \
        : "r"((a)[0]), "r"((a)[1]), "r"((a)[2]), "r"((a)[3]), "r"(b0v), "r"(b1v))

// ---------------- tiny setup kernels ----------------
__global__ void zero_counts_kernel() {
    if (threadIdx.x < EE) g_counts[threadIdx.x] = 0;
}

// fp32 router: 1 warp per token (exact, so argmax matches reference)
__global__ void router_kernel(const float* __restrict__ x,
                              const float* __restrict__ Wr,
                              const float* __restrict__ br) {
    int token = blockIdx.x * 8 + (threadIdx.x >> 5);
    int lane  = threadIdx.x & 31;
    const float* xr = x + (size_t)token * DD;
    float acc[EE];
#pragma unroll
    for (int e = 0; e < EE; e++) acc[e] = 0.f;
    for (int d = lane; d < DD; d += 32) {
        float xv = xr[d];
        const float4* w = (const float4*)(Wr + d * EE);
        float4 w0 = w[0], w1 = w[1];
        acc[0] += xv * w0.x; acc[1] += xv * w0.y;
        acc[2] += xv * w0.z; acc[3] += xv * w0.w;
        acc[4] += xv * w1.x; acc[5] += xv * w1.y;
        acc[6] += xv * w1.z; acc[7] += xv * w1.w;
    }
#pragma unroll
    for (int e = 0; e < EE; e++) {
#pragma unroll
        for (int o = 16; o; o >>= 1) acc[e] += __shfl_xor_sync(0xffffffffu, acc[e], o);
    }
    if (lane == 0) {
        float m = -1e30f; int best = 0;
#pragma unroll
        for (int e = 0; e < EE; e++) {
            float l = acc[e] + br[e];
            acc[e] = l;
            if (l > m) { m = l; best = e; }
        }
        float s = 0.f;
#pragma unroll
        for (int e = 0; e < EE; e++) s += expf(acc[e] - m);
        g_expert[token] = best;
        g_prob[token]   = 1.f / s;
        g_pos[token]    = atomicAdd(&g_counts[best], 1);
    }
}

__global__ void scan_kernel() {
    int s = 0;
#pragma unroll
    for (int e = 0; e < EE; e++) { g_off[e] = s; s += g_counts[e]; }
    g_off[EE] = s;
}

// gather tokens expert-contiguous, fp32 -> fp16
__global__ void gather_split_kernel(const float* __restrict__ x) {
    int token = blockIdx.x;
    int dst = g_off[g_expert[token]] + g_pos[token];
    if (threadIdx.x == 0) g_perm[dst] = token;
    const float4* s = (const float4*)(x + (size_t)token * DD);
    uint2* dh = (uint2*)(g_Xh + (size_t)dst * DD);
    for (int i = threadIdx.x; i < DD / 4; i += blockDim.x) {
        float4 v = s[i];
        __half2 h0, h1;
        h0.x = __float2half_rn(v.x); h0.y = __float2half_rn(v.y);
        h1.x = __float2half_rn(v.z); h1.y = __float2half_rn(v.w);
        uint2 ph;
        ph.x = *(uint32_t*)&h0; ph.y = *(uint32_t*)&h1;
        dh[i] = ph;
    }
}

// transpose: W [E][KD][ND] fp32 -> T [E][ND][KD] fp16 (round-to-nearest)
template <int KD, int ND>
__global__ void wsplit_kernel(const float* __restrict__ W,
                              __half* __restrict__ Th) {
    __shared__ float t[32][33];
    int e = blockIdx.z;
    int k0 = blockIdx.y * 32, n0 = blockIdx.x * 32;
    int tx = threadIdx.x, ty = threadIdx.y;
    const float* Wp = W + (size_t)e * KD * ND;
#pragma unroll
    for (int r = ty; r < 32; r += 8) t[r][tx] = Wp[(size_t)(k0 + r) * ND + n0 + tx];
    __syncthreads();
    size_t ob = (size_t)e * ND * KD;
#pragma unroll
    for (int r = ty; r < 32; r += 8) {
        Th[ob + (size_t)(n0 + r) * KD + k0 + tx] = __float2half_rn(t[tx][r]);
    }
}

// ---------------- grouped fp16 HMMA GEMM, 4-stage cp.async ring --------------
// Block tile 128(M) x 256(N), BK=64. 8 warps in 2(M) x 4(N), each warp 64x64.
// Single fp16 product, fp32 accumulation. One __syncthreads per k-chunk.
static constexpr int BM = 128, BN = 256, BK = 64;
static constexpr int A_T = BM * 128;                    // 16 KB A tile
static constexpr int B_T = BN * 128;                    // 32 KB B tile
static constexpr int STAGE = A_T + B_T;                 // 48 KB
static constexpr int SMEM_GEMM = 4 * STAGE;             // 192 KB

template <int K, int NOUT, bool FIRST>
__global__ void __launch_bounds__(256, 1) gemm_mma(
    const __half* __restrict__ A,
    const __half* __restrict__ B_all,
    const float* __restrict__ ball,
    __half* __restrict__ OutH,
    float* __restrict__ OutF)
{
    constexpr int KC = K / BK;

    int e = blockIdx.z;
    int rowBeg = g_off[e], rowEnd = g_off[e + 1];
    int row0 = rowBeg + blockIdx.y * BM;
    if (row0 >= rowEnd) return;
    int n0 = blockIdx.x * BN;

    const __half* BE = B_all + (size_t)e * NOUT * K;
    const float* bias = ball + (size_t)e * NOUT;

    extern __shared__ __align__(128) char smem[];
    uint32_t sb = smem_u32(smem);

    int tid = threadIdx.x;
    int wid = tid >> 5, lane = tid & 31;
    int warpM = wid & 1, warpN = wid >> 1;

    // ---- per-thread gmem->smem geometry (chunk-invariant) ----
    uint32_t smoA[4], smoB[8];
    int rkA[4], rkB[8];
#pragma unroll
    for (int j = 0; j < 4; j++) {
        int id = tid + j * 256;
        int r = id >> 3, c = id & 7;
        smoA[j] = (uint32_t)(r * 128 + ((c ^ (r & 7)) << 4));
        rkA[j] = r * K + c * 8;
    }
#pragma unroll
    for (int j = 0; j < 8; j++) {
        int id = tid + j * 256;          // 0..2047
        int r = id >> 3, c = id & 7;
        smoB[j] = (uint32_t)(r * 128 + ((c ^ (r & 7)) << 4));
        rkB[j] = r * K + c * 8;
    }

    // ---- ldmatrix per-thread geometry ----
    int rA  = warpM * 64 + (lane & 15);
    int cxA = lane >> 4;
    int sAx = rA & 7;
    int nrl = warpN * 64 + ((lane >> 4) << 3) + (lane & 7);
    int kbB = (lane >> 3) & 1;
    int sBx = nrl & 7;

    float acc[4][8][4];
#pragma unroll
    for (int i = 0; i < 4; i++)
#pragma unroll
        for (int j = 0; j < 8; j++)
#pragma unroll
            for (int q = 0; q < 4; q++) acc[i][j][q] = 0.f;

    size_t aRowOff = (size_t)row0 * K;
    size_t bRowOff = (size_t)n0 * K;

    auto issue = [&](int cn) {
        if (cn < KC) {
            int kk = cn * BK;
            uint32_t st = sb + (uint32_t)((cn & 3) * STAGE);
            const __half* Ap = A  + aRowOff + kk;
            const __half* Bp = BE + bRowOff + kk;
#pragma unroll
            for (int j = 0; j < 4; j++) cp16(st + smoA[j], Ap + rkA[j]);
#pragma unroll
            for (int j = 0; j < 8; j++) cp16(st + A_T + smoB[j], Bp + rkB[j]);
        }
        cp_commit();   // uniform group count even in the tail
    };

    issue(0); issue(1); issue(2);

    for (int c = 0; c < KC; c++) {
        cp_wait2();                    // stage c complete
        __syncthreads();               // visible to all warps; stage c-1 free
        issue(c + 3);                  // overwrites stage c-1's buffer
        uint32_t st = sb + (uint32_t)((c & 3) * STAGE);
        uint32_t aSm = st, bSm = st + A_T;
#pragma unroll
        for (int ks = 0; ks < 4; ks++) {
            uint32_t aro = (uint32_t)((((ks << 1) + cxA) ^ sAx) << 4);
            uint32_t bro = (uint32_t)((((ks << 1) + kbB) ^ sBx) << 4);
            uint32_t af[4][4];
#pragma unroll
            for (int i = 0; i < 4; i++) {
                uint32_t roff = (uint32_t)((rA + i * 16) * 128) + aro;
                LDSM4(af[i][0], af[i][1], af[i][2], af[i][3], aSm + roff);
            }
            uint32_t bf[4][4];
#pragma unroll
            for (int j = 0; j < 4; j++) {
                uint32_t roff = (uint32_t)((nrl + j * 16) * 128) + bro;
                LDSM4(bf[j][0], bf[j][1], bf[j][2], bf[j][3], bSm + roff);
            }
#pragma unroll
            for (int i = 0; i < 4; i++)
#pragma unroll
                for (int j = 0; j < 4; j++) {
                    MMA16816(acc[i][2 * j],     af[i], bf[j][0], bf[j][1]);
                    MMA16816(acc[i][2 * j + 1], af[i], bf[j][2], bf[j][3]);
                }
        }
    }

    // ---- epilogue ----
    int mb = row0 + warpM * 64;
    int nb = n0 + warpN * 64;
    int lr = lane >> 2, lc = (lane & 3) * 2;
    float2 blv[8];
#pragma unroll
    for (int j = 0; j < 8; j++) {
        int col = nb + j * 8 + lc;
        blv[j].x = __ldg(bias + col);
        blv[j].y = __ldg(bias + col + 1);
    }
#pragma unroll
    for (int i = 0; i < 4; i++) {
#pragma unroll
        for (int h = 0; h < 2; h++) {
            int row = mb + i * 16 + lr + h * 8;
            if (row < rowEnd) {
                if (FIRST) {
                    uint32_t* dh = (uint32_t*)(OutH + (size_t)row * NOUT);
#pragma unroll
                    for (int j = 0; j < 8; j++) {
                        int col = nb + j * 8 + lc;
                        float v0 = acc[i][j][2 * h]     + blv[j].x;
                        float v1 = acc[i][j][2 * h + 1] + blv[j].y;
                        v0 = fmaxf(v0, 0.f); v1 = fmaxf(v1, 0.f);
                        __half2 hh;
                        hh.x = __float2half_rn(v0); hh.y = __float2half_rn(v1);
                        dh[col >> 1] = *(uint32_t*)&hh;
                    }
                } else {
                    int tok = g_perm[row];
                    float p = g_prob[tok];
                    float2* dst = (float2*)(OutF + (size_t)tok * NOUT);
#pragma unroll
                    for (int j = 0; j < 8; j++) {
                        int col = nb + j * 8 + lc;
                        float2 o;
                        o.x = (acc[i][j][2 * h]     + blv[j].x) * p;
                        o.y = (acc[i][j][2 * h + 1] + blv[j].y) * p;
                        dst[col >> 1] = o;
                    }
                }
            }
        }
    }
}

// ---------------- entry ----------------
extern "C" void kernel_launch(void* const* d_in, const int* in_sizes, int n_in,
                              void* d_out, int out_size) {
    const float* x  = (const float*)d_in[0];
    const float* Wr = (const float*)d_in[1];
    const float* br = (const float*)d_in[2];
    const float* W1 = (const float*)d_in[3];
    const float* b1 = (const float*)d_in[4];
    const float* W2 = (const float*)d_in[5];
    const float* b2 = (const float*)d_in[6];
    float* out = (float*)d_out;

    __half *Xh, *Hh, *W1h, *W2h;
    cudaGetSymbolAddress((void**)&Xh, g_Xh);
    cudaGetSymbolAddress((void**)&Hh, g_Hh);
    cudaGetSymbolAddress((void**)&W1h, g_W1h);
    cudaGetSymbolAddress((void**)&W2h, g_W2h);

    cudaFuncSetAttribute(gemm_mma<DD, HH, true>,  cudaFuncAttributeMaxDynamicSharedMemorySize, SMEM_GEMM);
    cudaFuncSetAttribute(gemm_mma<HH, DD, false>, cudaFuncAttributeMaxDynamicSharedMemorySize, SMEM_GEMM);

    zero_counts_kernel<<<1, 32>>>();
    router_kernel<<<TT / 8, 256>>>(x, Wr, br);
    scan_kernel<<<1, 1>>>();
    gather_split_kernel<<<TT, 256>>>(x);

    dim3 tb(32, 8);
    wsplit_kernel<DD, HH><<<dim3(HH / 32, DD / 32, EE), tb>>>(W1, W1h);
    wsplit_kernel<HH, DD><<<dim3(DD / 32, HH / 32, EE), tb>>>(W2, W2h);

    dim3 g1(HH / BN, TT / BM, EE);
    gemm_mma<DD, HH, true><<<g1, 256, SMEM_GEMM>>>(Xh, W1h, b1, Hh, nullptr);
    dim3 g2(DD / BN, TT / BM, EE);
    gemm_mma<HH, DD, false><<<g2, 256, SMEM_GEMM>>>(Hh, W2h, b2, nullptr, out);
}

// round 7
// speedup vs baseline: 6.2337x; 1.1162x over previous
#include <cuda_runtime.h>
#include <cuda_fp16.h>
#include <math.h>
#include <stdint.h>

#define TT 8192
#define DD 1024
#define HH 2048
#define EE 8
#define PAD 256   // row padding so out-of-segment tile rows stay in-bounds

// ---------------- scratch (device globals: allocation-free) ----------------
__device__ int   g_expert[TT];
__device__ int   g_pos[TT];
__device__ float g_prob[TT];
__device__ int   g_counts[EE];
__device__ int   g_off[EE + 1];
__device__ int   g_perm[TT];

__device__ __half g_Xh[(TT + PAD) * DD];
__device__ __half g_Hh[(TT + PAD) * HH];
__device__ __half g_W1h[EE * DD * HH];  // W1 native [E][D][H], fp16
__device__ __half g_W2h[EE * HH * DD];  // W2 native [E][H][D], fp16

// ---------------- PTX helpers (plain compute_103-safe: sm_80-era ops only) ----
__device__ __forceinline__ uint32_t smem_u32(const void* p) {
    uint32_t a;
    asm("{ .reg .u64 t; cvta.to.shared.u64 t, %1; cvt.u32.u64 %0, t; }" : "=r"(a) : "l"(p));
    return a;
}
__device__ __forceinline__ void cp16(uint32_t dst, const void* src) {
    asm volatile("cp.async.cg.shared.global [%0], [%1], 16;" :: "r"(dst), "l"(src) : "memory");
}
__device__ __forceinline__ void cp_commit() { asm volatile("cp.async.commit_group;" ::: "memory"); }
__device__ __forceinline__ void cp_wait2()  { asm volatile("cp.async.wait_group 2;" ::: "memory"); }

#define LDSM4(r0, r1, r2, r3, addr) \
    asm volatile("ldmatrix.sync.aligned.m8n8.x4.shared.b16 {%0,%1,%2,%3}, [%4];" \
        : "=r"(r0), "=r"(r1), "=r"(r2), "=r"(r3) : "r"(addr))

#define LDSM4T(r0, r1, r2, r3, addr) \
    asm volatile("ldmatrix.sync.aligned.m8n8.x4.trans.shared.b16 {%0,%1,%2,%3}, [%4];" \
        : "=r"(r0), "=r"(r1), "=r"(r2), "=r"(r3) : "r"(addr))

#define MMA16816(d, a, b0v, b1v) \
    asm volatile("mma.sync.aligned.m16n8k16.row.col.f32.f16.f16.f32 " \
        "{%0,%1,%2,%3}, {%4,%5,%6,%7}, {%8,%9}, {%0,%1,%2,%3};" \
        : "+f"((d)[0]), "+f"((d)[1]), "+f"((d)[2]), "+f"((d)[3]) \
        : "r"((a)[0]), "r"((a)[1]), "r"((a)[2]), "r"((a)[3]), "r"(b0v), "r"(b1v))

// ---------------- tiny setup kernels ----------------
__global__ void zero_counts_kernel() {
    if (threadIdx.x < EE) g_counts[threadIdx.x] = 0;
}

// fp32 router: 1 warp per token (exact, so argmax matches reference)
__global__ void router_kernel(const float* __restrict__ x,
                              const float* __restrict__ Wr,
                              const float* __restrict__ br) {
    int token = blockIdx.x * 8 + (threadIdx.x >> 5);
    int lane  = threadIdx.x & 31;
    const float* xr = x + (size_t)token * DD;
    float acc[EE];
#pragma unroll
    for (int e = 0; e < EE; e++) acc[e] = 0.f;
    for (int d = lane; d < DD; d += 32) {
        float xv = xr[d];
        const float4* w = (const float4*)(Wr + d * EE);
        float4 w0 = w[0], w1 = w[1];
        acc[0] += xv * w0.x; acc[1] += xv * w0.y;
        acc[2] += xv * w0.z; acc[3] += xv * w0.w;
        acc[4] += xv * w1.x; acc[5] += xv * w1.y;
        acc[6] += xv * w1.z; acc[7] += xv * w1.w;
    }
#pragma unroll
    for (int e = 0; e < EE; e++) {
#pragma unroll
        for (int o = 16; o; o >>= 1) acc[e] += __shfl_xor_sync(0xffffffffu, acc[e], o);
    }
    if (lane == 0) {
        float m = -1e30f; int best = 0;
#pragma unroll
        for (int e = 0; e < EE; e++) {
            float l = acc[e] + br[e];
            acc[e] = l;
            if (l > m) { m = l; best = e; }
        }
        float s = 0.f;
#pragma unroll
        for (int e = 0; e < EE; e++) s += expf(acc[e] - m);
        g_expert[token] = best;
        g_prob[token]   = 1.f / s;
        g_pos[token]    = atomicAdd(&g_counts[best], 1);
    }
}

__global__ void scan_kernel() {
    int s = 0;
#pragma unroll
    for (int e = 0; e < EE; e++) { g_off[e] = s; s += g_counts[e]; }
    g_off[EE] = s;
}

// gather tokens expert-contiguous, fp32 -> fp16. 32 tokens per block.
__global__ void gather_split_kernel(const float* __restrict__ x) {
    int t0 = blockIdx.x * 32;
    for (int t = 0; t < 32; t++) {
        int token = t0 + t;
        int dst = g_off[g_expert[token]] + g_pos[token];
        if (threadIdx.x == 0) g_perm[dst] = token;
        const float4* s = (const float4*)(x + (size_t)token * DD);
        uint2* dh = (uint2*)(g_Xh + (size_t)dst * DD);
        for (int i = threadIdx.x; i < DD / 4; i += blockDim.x) {
            float4 v = s[i];
            __half2 h0, h1;
            h0.x = __float2half_rn(v.x); h0.y = __float2half_rn(v.y);
            h1.x = __float2half_rn(v.z); h1.y = __float2half_rn(v.w);
            uint2 ph;
            ph.x = *(uint32_t*)&h0; ph.y = *(uint32_t*)&h1;
            dh[i] = ph;
        }
    }
}

// streaming convert fp32 -> fp16 (no transpose). grid.y: 0 -> W1, 1 -> W2.
__global__ void wconv_kernel(const float* __restrict__ W1, const float* __restrict__ W2,
                             __half* __restrict__ T1, __half* __restrict__ T2) {
    const float* W = blockIdx.y ? W2 : W1;
    __half* T = blockIdx.y ? T2 : T1;
    size_t i = ((size_t)blockIdx.x * blockDim.x + threadIdx.x) * 8;
    const float4* s = (const float4*)(W + i);
    float4 v0 = s[0], v1 = s[1];
    __half2 a, b, c, d;
    a.x = __float2half_rn(v0.x); a.y = __float2half_rn(v0.y);
    b.x = __float2half_rn(v0.z); b.y = __float2half_rn(v0.w);
    c.x = __float2half_rn(v1.x); c.y = __float2half_rn(v1.y);
    d.x = __float2half_rn(v1.z); d.y = __float2half_rn(v1.w);
    uint4 o;
    o.x = *(uint32_t*)&a; o.y = *(uint32_t*)&b;
    o.z = *(uint32_t*)&c; o.w = *(uint32_t*)&d;
    *(uint4*)(T + i) = o;
}

// ---------------- grouped fp16 HMMA GEMM, 4-stage cp.async ring --------------
// Block tile 128(M) x 256(N), BK=64. 8 warps in 2(M) x 4(N), each warp 64x64.
// A: [rows][K] row-major, 128B smem rows, non-trans ldmatrix.
// B: native [K][NOUT]; smem tile [64 x 512B], trans ldmatrix (no pre-transpose).
static constexpr int BM = 128, BN = 256, BK = 64;
static constexpr int A_T = BM * 128;                    // 16 KB A tile
static constexpr int B_T = BK * 512;                    // 32 KB B tile
static constexpr int STAGE = A_T + B_T;                 // 48 KB
static constexpr int SMEM_GEMM = 4 * STAGE;             // 192 KB

template <int K, int NOUT, bool FIRST>
__global__ void __launch_bounds__(256, 1) gemm_mma(
    const __half* __restrict__ A,
    const __half* __restrict__ B_all,
    const float* __restrict__ ball,
    __half* __restrict__ OutH,
    float* __restrict__ OutF)
{
    constexpr int KC = K / BK;

    int e = blockIdx.z;
    int rowBeg = g_off[e], rowEnd = g_off[e + 1];
    int row0 = rowBeg + blockIdx.y * BM;
    if (row0 >= rowEnd) return;
    int n0 = blockIdx.x * BN;

    const __half* BE = B_all + (size_t)e * K * NOUT;
    const float* bias = ball + (size_t)e * NOUT;

    extern __shared__ __align__(128) char smem[];
    uint32_t sb = smem_u32(smem);

    int tid = threadIdx.x;
    int wid = tid >> 5, lane = tid & 31;
    int warpM = wid & 1, warpN = wid >> 1;

    // ---- per-thread gmem->smem geometry (chunk-invariant) ----
    uint32_t smoA[4]; int rkA[4];
#pragma unroll
    for (int j = 0; j < 4; j++) {
        int id = tid + j * 256;
        int r = id >> 3, c = id & 7;
        smoA[j] = (uint32_t)(r * 128 + ((c ^ (r & 7)) << 4));
        rkA[j] = r * K + c * 8;
    }
    // B: 2048 chunks of 16B over [64 rows][32 chunks]
    uint32_t smoB[8]; int rkB[8];
#pragma unroll
    for (int j = 0; j < 8; j++) {
        int id = tid + j * 256;
        int r = id >> 5, c = id & 31;
        smoB[j] = (uint32_t)(r * 512 + ((c ^ (r & 7)) << 4));
        rkB[j] = r * NOUT + c * 8;
    }

    // ---- ldmatrix per-thread geometry ----
    int rA  = warpM * 64 + (lane & 15);
    int cxA = lane >> 4;
    int sAx = rA & 7;
    // B (trans): lanes 0-7 k0-7, 8-15 k8-15, 16-23 k0-7(+n8), 24-31 k8-15(+n8)
    int bRow = (lane & 7) + (((lane >> 3) & 1) << 3);   // 0..15
    uint32_t bByte = (uint32_t)bRow * 512;
    int c16b = warpN * 8 + (lane >> 4);                 // +2*j per n16-tile
    int sBx = lane & 7;

    float acc[4][8][4];
#pragma unroll
    for (int i = 0; i < 4; i++)
#pragma unroll
        for (int j = 0; j < 8; j++)
#pragma unroll
            for (int q = 0; q < 4; q++) acc[i][j][q] = 0.f;

    size_t aRowOff = (size_t)row0 * K;

    auto issue = [&](int cn) {
        if (cn < KC) {
            int kk = cn * BK;
            uint32_t st = sb + (uint32_t)((cn & 3) * STAGE);
            const __half* Ap = A + aRowOff + kk;
            const __half* Bp = BE + (size_t)kk * NOUT + n0;
#pragma unroll
            for (int j = 0; j < 4; j++) cp16(st + smoA[j], Ap + rkA[j]);
#pragma unroll
            for (int j = 0; j < 8; j++) cp16(st + A_T + smoB[j], Bp + rkB[j]);
        }
        cp_commit();   // uniform group count even in the tail
    };

    issue(0); issue(1); issue(2);

    for (int c = 0; c < KC; c++) {
        cp_wait2();                    // stage c complete
        __syncthreads();               // visible to all warps; stage c-1 free
        issue(c + 3);                  // overwrites stage c-1's buffer
        uint32_t st = sb + (uint32_t)((c & 3) * STAGE);
        uint32_t aSm = st, bSm = st + A_T;
#pragma unroll
        for (int ks = 0; ks < 4; ks++) {
            uint32_t aro = (uint32_t)((((ks << 1) + cxA) ^ sAx) << 4);
            uint32_t af[4][4];
#pragma unroll
            for (int i = 0; i < 4; i++) {
                uint32_t roff = (uint32_t)((rA + i * 16) * 128) + aro;
                LDSM4(af[i][0], af[i][1], af[i][2], af[i][3], aSm + roff);
            }
            uint32_t bf[4][4];
            uint32_t bks = bSm + (uint32_t)(ks * 8192) + bByte;
#pragma unroll
            for (int j = 0; j < 4; j++) {
                uint32_t addr = bks + (uint32_t)(((c16b + 2 * j) ^ sBx) << 4);
                LDSM4T(bf[j][0], bf[j][1], bf[j][2], bf[j][3], addr);
            }
#pragma unroll
            for (int i = 0; i < 4; i++)
#pragma unroll
                for (int j = 0; j < 4; j++) {
                    MMA16816(acc[i][2 * j],     af[i], bf[j][0], bf[j][1]);
                    MMA16816(acc[i][2 * j + 1], af[i], bf[j][2], bf[j][3]);
                }
        }
    }

    // ---- epilogue ----
    int mb = row0 + warpM * 64;
    int nb = n0 + warpN * 64;
    int lr = lane >> 2, lc = (lane & 3) * 2;
    float2 blv[8];
#pragma unroll
    for (int j = 0; j < 8; j++) {
        int col = nb + j * 8 + lc;
        blv[j].x = __ldg(bias + col);
        blv[j].y = __ldg(bias + col + 1);
    }
#pragma unroll
    for (int i = 0; i < 4; i++) {
#pragma unroll
        for (int h = 0; h < 2; h++) {
            int row = mb + i * 16 + lr + h * 8;
            if (row < rowEnd) {
                if (FIRST) {
                    uint32_t* dh = (uint32_t*)(OutH + (size_t)row * NOUT);
#pragma unroll
                    for (int j = 0; j < 8; j++) {
                        int col = nb + j * 8 + lc;
                        float v0 = acc[i][j][2 * h]     + blv[j].x;
                        float v1 = acc[i][j][2 * h + 1] + blv[j].y;
                        v0 = fmaxf(v0, 0.f); v1 = fmaxf(v1, 0.f);
                        __half2 hh;
                        hh.x = __float2half_rn(v0); hh.y = __float2half_rn(v1);
                        dh[col >> 1] = *(uint32_t*)&hh;
                    }
                } else {
                    int tok = g_perm[row];
                    float p = g_prob[tok];
                    float2* dst = (float2*)(OutF + (size_t)tok * NOUT);
#pragma unroll
                    for (int j = 0; j < 8; j++) {
                        int col = nb + j * 8 + lc;
                        float2 o;
                        o.x = (acc[i][j][2 * h]     + blv[j].x) * p;
                        o.y = (acc[i][j][2 * h + 1] + blv[j].y) * p;
                        dst[col >> 1] = o;
                    }
                }
            }
        }
    }
}

// ---------------- entry ----------------
extern "C" void kernel_launch(void* const* d_in, const int* in_sizes, int n_in,
                              void* d_out, int out_size) {
    const float* x  = (const float*)d_in[0];
    const float* Wr = (const float*)d_in[1];
    const float* br = (const float*)d_in[2];
    const float* W1 = (const float*)d_in[3];
    const float* b1 = (const float*)d_in[4];
    const float* W2 = (const float*)d_in[5];
    const float* b2 = (const float*)d_in[6];
    float* out = (float*)d_out;

    __half *Xh, *Hh, *W1h, *W2h;
    cudaGetSymbolAddress((void**)&Xh, g_Xh);
    cudaGetSymbolAddress((void**)&Hh, g_Hh);
    cudaGetSymbolAddress((void**)&W1h, g_W1h);
    cudaGetSymbolAddress((void**)&W2h, g_W2h);

    cudaFuncSetAttribute(gemm_mma<DD, HH, true>,  cudaFuncAttributeMaxDynamicSharedMemorySize, SMEM_GEMM);
    cudaFuncSetAttribute(gemm_mma<HH, DD, false>, cudaFuncAttributeMaxDynamicSharedMemorySize, SMEM_GEMM);

    zero_counts_kernel<<<1, 32>>>();
    router_kernel<<<TT / 8, 256>>>(x, Wr, br);
    scan_kernel<<<1, 1>>>();
    gather_split_kernel<<<TT / 32, 256>>>(x);

    // 16.8M elems per weight, 8 per thread -> 8192 blocks x 256 threads, y=0/1
    wconv_kernel<<<dim3(8192, 2), 256>>>(W1, W2, W1h, W2h);

    dim3 g1(HH / BN, TT / BM, EE);
    gemm_mma<DD, HH, true><<<g1, 256, SMEM_GEMM>>>(Xh, W1h, b1, Hh, nullptr);
    dim3 g2(DD / BN, TT / BM, EE);
    gemm_mma<HH, DD, false><<<g2, 256, SMEM_GEMM>>>(Hh, W2h, b2, nullptr, out);
}

// round 8
// speedup vs baseline: 6.3017x; 1.0109x over previous
#include <cuda_runtime.h>
#include <cuda_fp16.h>
#include <math.h>
#include <stdint.h>

#define TT 8192
#define DD 1024
#define HH 2048
#define EE 8
#define PAD 256   // row padding so out-of-segment tile rows stay in-bounds

// ---------------- scratch (device globals: allocation-free) ----------------
__device__ int   g_expert[TT];
__device__ int   g_pos[TT];
__device__ float g_prob[TT];
__device__ int   g_counts[EE];
__device__ int   g_off[EE + 1];
__device__ int   g_perm[TT];

__device__ __half g_Xh[(TT + PAD) * DD];
__device__ __half g_Hh[(TT + PAD) * HH];
__device__ __half g_W1h[EE * DD * HH];  // W1 native [E][D][H], fp16
__device__ __half g_W2h[EE * HH * DD];  // W2 native [E][H][D], fp16

// ---------------- PTX helpers (plain compute_103-safe: sm_80-era ops only) ----
__device__ __forceinline__ uint32_t smem_u32(const void* p) {
    uint32_t a;
    asm("{ .reg .u64 t; cvta.to.shared.u64 t, %1; cvt.u32.u64 %0, t; }" : "=r"(a) : "l"(p));
    return a;
}
__device__ __forceinline__ void cp16(uint32_t dst, const void* src) {
    asm volatile("cp.async.cg.shared.global [%0], [%1], 16;" :: "r"(dst), "l"(src) : "memory");
}
__device__ __forceinline__ void cp_commit() { asm volatile("cp.async.commit_group;" ::: "memory"); }
__device__ __forceinline__ void cp_wait2()  { asm volatile("cp.async.wait_group 2;" ::: "memory"); }

#define LDSM4(r0, r1, r2, r3, addr) \
    asm volatile("ldmatrix.sync.aligned.m8n8.x4.shared.b16 {%0,%1,%2,%3}, [%4];" \
        : "=r"(r0), "=r"(r1), "=r"(r2), "=r"(r3) : "r"(addr))

#define LDSM4T(r0, r1, r2, r3, addr) \
    asm volatile("ldmatrix.sync.aligned.m8n8.x4.trans.shared.b16 {%0,%1,%2,%3}, [%4];" \
        : "=r"(r0), "=r"(r1), "=r"(r2), "=r"(r3) : "r"(addr))

#define MMA16816(d, a, b0v, b1v) \
    asm volatile("mma.sync.aligned.m16n8k16.row.col.f32.f16.f16.f32 " \
        "{%0,%1,%2,%3}, {%4,%5,%6,%7}, {%8,%9}, {%0,%1,%2,%3};" \
        : "+f"((d)[0]), "+f"((d)[1]), "+f"((d)[2]), "+f"((d)[3]) \
        : "r"((a)[0]), "r"((a)[1]), "r"((a)[2]), "r"((a)[3]), "r"(b0v), "r"(b1v))

// ---------------- tiny setup kernels ----------------
__global__ void zero_counts_kernel() {
    if (threadIdx.x < EE) g_counts[threadIdx.x] = 0;
}

// Fused: blocks [0,1024) = fp32 router (1 warp/token, exact);
//        blocks [1024, 1024+16384) = streaming W fp32->fp16 convert.
__global__ void router_wconv_kernel(const float* __restrict__ x,
                                    const float* __restrict__ Wr,
                                    const float* __restrict__ br,
                                    const float* __restrict__ W1,
                                    const float* __restrict__ W2,
                                    __half* __restrict__ T1,
                                    __half* __restrict__ T2) {
    int b = blockIdx.x;
    if (b < TT / 8) {
        // ---- router ----
        int token = b * 8 + (threadIdx.x >> 5);
        int lane  = threadIdx.x & 31;
        const float* xr = x + (size_t)token * DD;
        float acc[EE];
#pragma unroll
        for (int e = 0; e < EE; e++) acc[e] = 0.f;
        for (int d = lane; d < DD; d += 32) {
            float xv = xr[d];
            const float4* w = (const float4*)(Wr + d * EE);
            float4 w0 = w[0], w1 = w[1];
            acc[0] += xv * w0.x; acc[1] += xv * w0.y;
            acc[2] += xv * w0.z; acc[3] += xv * w0.w;
            acc[4] += xv * w1.x; acc[5] += xv * w1.y;
            acc[6] += xv * w1.z; acc[7] += xv * w1.w;
        }
#pragma unroll
        for (int e = 0; e < EE; e++) {
#pragma unroll
            for (int o = 16; o; o >>= 1) acc[e] += __shfl_xor_sync(0xffffffffu, acc[e], o);
        }
        if (lane == 0) {
            float m = -1e30f; int best = 0;
#pragma unroll
            for (int e = 0; e < EE; e++) {
                float l = acc[e] + br[e];
                acc[e] = l;
                if (l > m) { m = l; best = e; }
            }
            float s = 0.f;
#pragma unroll
            for (int e = 0; e < EE; e++) s += expf(acc[e] - m);
            g_expert[token] = best;
            g_prob[token]   = 1.f / s;
            g_pos[token]    = atomicAdd(&g_counts[best], 1);
        }
    } else {
        // ---- weight convert (no deps; interleave W1/W2 for balance) ----
        int wb = b - TT / 8;                 // 0..16383
        const float* W = (wb & 1) ? W2 : W1;
        __half* T = (wb & 1) ? T2 : T1;
        size_t i = (((size_t)(wb >> 1) * blockDim.x) + threadIdx.x) * 8;
        const float4* s = (const float4*)(W + i);
        float4 v0 = s[0], v1 = s[1];
        __half2 a2, b2, c2, d2;
        a2.x = __float2half_rn(v0.x); a2.y = __float2half_rn(v0.y);
        b2.x = __float2half_rn(v0.z); b2.y = __float2half_rn(v0.w);
        c2.x = __float2half_rn(v1.x); c2.y = __float2half_rn(v1.y);
        d2.x = __float2half_rn(v1.z); d2.y = __float2half_rn(v1.w);
        uint4 o;
        o.x = *(uint32_t*)&a2; o.y = *(uint32_t*)&b2;
        o.z = *(uint32_t*)&c2; o.w = *(uint32_t*)&d2;
        *(uint4*)(T + i) = o;
    }
}

__global__ void scan_kernel() {
    int s = 0;
#pragma unroll
    for (int e = 0; e < EE; e++) { g_off[e] = s; s += g_counts[e]; }
    g_off[EE] = s;
}

// gather tokens expert-contiguous, fp32 -> fp16. One token per block.
__global__ void gather_split_kernel(const float* __restrict__ x) {
    int token = blockIdx.x;
    int dst = g_off[g_expert[token]] + g_pos[token];
    if (threadIdx.x == 0) g_perm[dst] = token;
    const float4* s = (const float4*)(x + (size_t)token * DD);
    uint2* dh = (uint2*)(g_Xh + (size_t)dst * DD);
    for (int i = threadIdx.x; i < DD / 4; i += blockDim.x) {
        float4 v = s[i];
        __half2 h0, h1;
        h0.x = __float2half_rn(v.x); h0.y = __float2half_rn(v.y);
        h1.x = __float2half_rn(v.z); h1.y = __float2half_rn(v.w);
        uint2 ph;
        ph.x = *(uint32_t*)&h0; ph.y = *(uint32_t*)&h1;
        dh[i] = ph;
    }
}

// ---------------- grouped fp16 HMMA GEMM, 4-stage cp.async ring --------------
// Block tile 128(M) x 256(N), BK=64. 8 warps in 2(M) x 4(N), each warp 64x64.
// A: [rows][K] row-major, 128B smem rows, non-trans ldmatrix.
// B: native [K][NOUT]; smem tile [64 x 512B], trans ldmatrix (no pre-transpose).
static constexpr int BM = 128, BN = 256, BK = 64;
static constexpr int A_T = BM * 128;                    // 16 KB A tile
static constexpr int B_T = BK * 512;                    // 32 KB B tile
static constexpr int STAGE = A_T + B_T;                 // 48 KB
static constexpr int SMEM_GEMM = 4 * STAGE;             // 192 KB

template <int K, int NOUT, bool FIRST>
__global__ void __launch_bounds__(256, 1) gemm_mma(
    const __half* __restrict__ A,
    const __half* __restrict__ B_all,
    const float* __restrict__ ball,
    __half* __restrict__ OutH,
    float* __restrict__ OutF)
{
    constexpr int KC = K / BK;

    int e = blockIdx.z;
    int rowBeg = g_off[e], rowEnd = g_off[e + 1];
    int row0 = rowBeg + blockIdx.y * BM;
    if (row0 >= rowEnd) return;
    int n0 = blockIdx.x * BN;

    const __half* BE = B_all + (size_t)e * K * NOUT;
    const float* bias = ball + (size_t)e * NOUT;

    extern __shared__ __align__(128) char smem[];
    uint32_t sb = smem_u32(smem);

    int tid = threadIdx.x;
    int wid = tid >> 5, lane = tid & 31;
    int warpM = wid & 1, warpN = wid >> 1;

    // ---- per-thread gmem->smem geometry (chunk-invariant) ----
    uint32_t smoA[4]; int rkA[4];
#pragma unroll
    for (int j = 0; j < 4; j++) {
        int id = tid + j * 256;
        int r = id >> 3, c = id & 7;
        smoA[j] = (uint32_t)(r * 128 + ((c ^ (r & 7)) << 4));
        rkA[j] = r * K + c * 8;
    }
    // B: 2048 chunks of 16B over [64 rows][32 chunks]
    uint32_t smoB[8]; int rkB[8];
#pragma unroll
    for (int j = 0; j < 8; j++) {
        int id = tid + j * 256;
        int r = id >> 5, c = id & 31;
        smoB[j] = (uint32_t)(r * 512 + ((c ^ (r & 7)) << 4));
        rkB[j] = r * NOUT + c * 8;
    }

    // ---- ldmatrix per-thread geometry ----
    int rA  = warpM * 64 + (lane & 15);
    int cxA = lane >> 4;
    int sAx = rA & 7;
    // B (trans): lanes 0-7 k0-7, 8-15 k8-15, 16-23 k0-7(+n8), 24-31 k8-15(+n8)
    int bRow = (lane & 7) + (((lane >> 3) & 1) << 3);   // 0..15
    uint32_t bByte = (uint32_t)bRow * 512;
    int c16b = warpN * 8 + (lane >> 4);                 // +2*j per n16-tile
    int sBx = lane & 7;

    float acc[4][8][4];
#pragma unroll
    for (int i = 0; i < 4; i++)
#pragma unroll
        for (int j = 0; j < 8; j++)
#pragma unroll
            for (int q = 0; q < 4; q++) acc[i][j][q] = 0.f;

    size_t aRowOff = (size_t)row0 * K;

    auto issue = [&](int cn) {
        if (cn < KC) {
            int kk = cn * BK;
            uint32_t st = sb + (uint32_t)((cn & 3) * STAGE);
            const __half* Ap = A + aRowOff + kk;
            const __half* Bp = BE + (size_t)kk * NOUT + n0;
#pragma unroll
            for (int j = 0; j < 4; j++) cp16(st + smoA[j], Ap + rkA[j]);
#pragma unroll
            for (int j = 0; j < 8; j++) cp16(st + A_T + smoB[j], Bp + rkB[j]);
        }
        cp_commit();   // uniform group count even in the tail
    };

    issue(0); issue(1); issue(2);

    for (int c = 0; c < KC; c++) {
        cp_wait2();                    // stage c complete
        __syncthreads();               // visible to all warps; stage c-1 free
        issue(c + 3);                  // overwrites stage c-1's buffer
        uint32_t st = sb + (uint32_t)((c & 3) * STAGE);
        uint32_t aSm = st, bSm = st + A_T;
#pragma unroll
        for (int ks = 0; ks < 4; ks++) {
            uint32_t aro = (uint32_t)((((ks << 1) + cxA) ^ sAx) << 4);
            uint32_t af[4][4];
#pragma unroll
            for (int i = 0; i < 4; i++) {
                uint32_t roff = (uint32_t)((rA + i * 16) * 128) + aro;
                LDSM4(af[i][0], af[i][1], af[i][2], af[i][3], aSm + roff);
            }
            uint32_t bf[4][4];
            uint32_t bks = bSm + (uint32_t)(ks * 8192) + bByte;
#pragma unroll
            for (int j = 0; j < 4; j++) {
                uint32_t addr = bks + (uint32_t)(((c16b + 2 * j) ^ sBx) << 4);
                LDSM4T(bf[j][0], bf[j][1], bf[j][2], bf[j][3], addr);
            }
#pragma unroll
            for (int i = 0; i < 4; i++)
#pragma unroll
                for (int j = 0; j < 4; j++) {
                    MMA16816(acc[i][2 * j],     af[i], bf[j][0], bf[j][1]);
                    MMA16816(acc[i][2 * j + 1], af[i], bf[j][2], bf[j][3]);
                }
        }
    }

    // ---- epilogue ----
    int mb = row0 + warpM * 64;
    int nb = n0 + warpN * 64;
    int lr = lane >> 2, lc = (lane & 3) * 2;
    float2 blv[8];
#pragma unroll
    for (int j = 0; j < 8; j++) {
        int col = nb + j * 8 + lc;
        blv[j].x = __ldg(bias + col);
        blv[j].y = __ldg(bias + col + 1);
    }
#pragma unroll
    for (int i = 0; i < 4; i++) {
#pragma unroll
        for (int h = 0; h < 2; h++) {
            int row = mb + i * 16 + lr + h * 8;
            if (row < rowEnd) {
                if (FIRST) {
                    uint32_t* dh = (uint32_t*)(OutH + (size_t)row * NOUT);
#pragma unroll
                    for (int j = 0; j < 8; j++) {
                        int col = nb + j * 8 + lc;
                        float v0 = acc[i][j][2 * h]     + blv[j].x;
                        float v1 = acc[i][j][2 * h + 1] + blv[j].y;
                        v0 = fmaxf(v0, 0.f); v1 = fmaxf(v1, 0.f);
                        __half2 hh;
                        hh.x = __float2half_rn(v0); hh.y = __float2half_rn(v1);
                        dh[col >> 1] = *(uint32_t*)&hh;
                    }
                } else {
                    int tok = g_perm[row];
                    float p = g_prob[tok];
                    float2* dst = (float2*)(OutF + (size_t)tok * NOUT);
#pragma unroll
                    for (int j = 0; j < 8; j++) {
                        int col = nb + j * 8 + lc;
                        float2 o;
                        o.x = (acc[i][j][2 * h]     + blv[j].x) * p;
                        o.y = (acc[i][j][2 * h + 1] + blv[j].y) * p;
                        dst[col >> 1] = o;
                    }
                }
            }
        }
    }
}

// ---------------- entry ----------------
extern "C" void kernel_launch(void* const* d_in, const int* in_sizes, int n_in,
                              void* d_out, int out_size) {
    const float* x  = (const float*)d_in[0];
    const float* Wr = (const float*)d_in[1];
    const float* br = (const float*)d_in[2];
    const float* W1 = (const float*)d_in[3];
    const float* b1 = (const float*)d_in[4];
    const float* W2 = (const float*)d_in[5];
    const float* b2 = (const float*)d_in[6];
    float* out = (float*)d_out;

    __half *Xh, *Hh, *W1h, *W2h;
    cudaGetSymbolAddress((void**)&Xh, g_Xh);
    cudaGetSymbolAddress((void**)&Hh, g_Hh);
    cudaGetSymbolAddress((void**)&W1h, g_W1h);
    cudaGetSymbolAddress((void**)&W2h, g_W2h);

    cudaFuncSetAttribute(gemm_mma<DD, HH, true>,  cudaFuncAttributeMaxDynamicSharedMemorySize, SMEM_GEMM);
    cudaFuncSetAttribute(gemm_mma<HH, DD, false>, cudaFuncAttributeMaxDynamicSharedMemorySize, SMEM_GEMM);

    zero_counts_kernel<<<1, 32>>>();
    // router blocks (1024) + wconv blocks (2 x 8192): one launch
    router_wconv_kernel<<<TT / 8 + 2 * 8192, 256>>>(x, Wr, br, W1, W2, W1h, W2h);
    scan_kernel<<<1, 1>>>();
    gather_split_kernel<<<TT, 256>>>(x);

    dim3 g1(HH / BN, TT / BM, EE);
    gemm_mma<DD, HH, true><<<g1, 256, SMEM_GEMM>>>(Xh, W1h, b1, Hh, nullptr);
    dim3 g2(DD / BN, TT / BM, EE);
    gemm_mma<HH, DD, false><<<g2, 256, SMEM_GEMM>>>(Hh, W2h, b2, nullptr, out);
}

// round 9
// speedup vs baseline: 6.5087x; 1.0329x over previous
#include <cuda_runtime.h>
#include <cuda_fp16.h>
#include <math.h>
#include <stdint.h>

#define TT 8192
#define DD 1024
#define HH 2048
#define EE 8
#define PAD 256   // row padding so out-of-segment tile rows stay in-bounds

// ---------------- scratch (device globals: allocation-free) ----------------
__device__ int   g_expert[TT];
__device__ int   g_pos[TT];
__device__ float g_prob[TT];
__device__ int   g_counts[EE];
__device__ int   g_off[EE + 1];
__device__ int   g_perm[TT];

__device__ __half g_Xh[(TT + PAD) * DD];
__device__ __half g_Hh[(TT + PAD) * HH];
__device__ __half g_W1h[EE * DD * HH];  // W1 native [E][D][H], fp16
__device__ __half g_W2h[EE * HH * DD];  // W2 native [E][H][D], fp16

// ---------------- PTX helpers (plain compute_103-safe: sm_80-era ops only) ----
__device__ __forceinline__ uint32_t smem_u32(const void* p) {
    uint32_t a;
    asm("{ .reg .u64 t; cvta.to.shared.u64 t, %1; cvt.u32.u64 %0, t; }" : "=r"(a) : "l"(p));
    return a;
}
__device__ __forceinline__ void cp16(uint32_t dst, const void* src) {
    asm volatile("cp.async.cg.shared.global [%0], [%1], 16;" :: "r"(dst), "l"(src) : "memory");
}
__device__ __forceinline__ void cp_commit() { asm volatile("cp.async.commit_group;" ::: "memory"); }
__device__ __forceinline__ void cp_wait2()  { asm volatile("cp.async.wait_group 2;" ::: "memory"); }

#define LDSM4(r0, r1, r2, r3, addr) \
    asm volatile("ldmatrix.sync.aligned.m8n8.x4.shared.b16 {%0,%1,%2,%3}, [%4];" \
        : "=r"(r0), "=r"(r1), "=r"(r2), "=r"(r3) : "r"(addr))

#define LDSM4T(r0, r1, r2, r3, addr) \
    asm volatile("ldmatrix.sync.aligned.m8n8.x4.trans.shared.b16 {%0,%1,%2,%3}, [%4];" \
        : "=r"(r0), "=r"(r1), "=r"(r2), "=r"(r3) : "r"(addr))

#define MMA16816(d, a, b0v, b1v) \
    asm volatile("mma.sync.aligned.m16n8k16.row.col.f32.f16.f16.f32 " \
        "{%0,%1,%2,%3}, {%4,%5,%6,%7}, {%8,%9}, {%0,%1,%2,%3};" \
        : "+f"((d)[0]), "+f"((d)[1]), "+f"((d)[2]), "+f"((d)[3]) \
        : "r"((a)[0]), "r"((a)[1]), "r"((a)[2]), "r"((a)[3]), "r"(b0v), "r"(b1v))

// ---------------- tiny setup kernels ----------------
__global__ void zero_counts_kernel() {
    if (threadIdx.x < EE) g_counts[threadIdx.x] = 0;
}

// fp32 -> fp16 convert of 8 contiguous elems at element index i*8
__device__ __forceinline__ void conv8(const float* __restrict__ W,
                                      __half* __restrict__ T, size_t i8) {
    const float4* s = (const float4*)(W + i8);
    float4 v0 = s[0], v1 = s[1];
    __half2 a2, b2, c2, d2;
    a2.x = __float2half_rn(v0.x); a2.y = __float2half_rn(v0.y);
    b2.x = __float2half_rn(v0.z); b2.y = __float2half_rn(v0.w);
    c2.x = __float2half_rn(v1.x); c2.y = __float2half_rn(v1.y);
    d2.x = __float2half_rn(v1.z); d2.y = __float2half_rn(v1.w);
    uint4 o;
    o.x = *(uint32_t*)&a2; o.y = *(uint32_t*)&b2;
    o.z = *(uint32_t*)&c2; o.w = *(uint32_t*)&d2;
    *(uint4*)(T + i8) = o;
}

// Fused: blocks [0,1024) = fp32 router (Wr staged in smem, exact fp32 math);
//        blocks [1024, 1024+8192) = streaming W1 fp32->fp16 convert.
__global__ void router_wconv_kernel(const float* __restrict__ x,
                                    const float* __restrict__ Wr,
                                    const float* __restrict__ br,
                                    const float* __restrict__ W1,
                                    __half* __restrict__ T1) {
    int b = blockIdx.x;
    if (b < TT / 8) {
        // ---- router: stage Wr (32 KB) in smem once per block ----
        __shared__ float sWr[DD * EE];
        for (int i = threadIdx.x; i < DD * EE / 4; i += 256)
            ((float4*)sWr)[i] = ((const float4*)Wr)[i];
        __syncthreads();

        int token = b * 8 + (threadIdx.x >> 5);
        int lane  = threadIdx.x & 31;
        const float* xr = x + (size_t)token * DD;
        float acc[EE];
#pragma unroll
        for (int e = 0; e < EE; e++) acc[e] = 0.f;
        for (int d = lane; d < DD; d += 32) {
            float xv = xr[d];
            const float4* w = (const float4*)(sWr + d * EE);
            float4 w0 = w[0], w1 = w[1];
            acc[0] += xv * w0.x; acc[1] += xv * w0.y;
            acc[2] += xv * w0.z; acc[3] += xv * w0.w;
            acc[4] += xv * w1.x; acc[5] += xv * w1.y;
            acc[6] += xv * w1.z; acc[7] += xv * w1.w;
        }
#pragma unroll
        for (int e = 0; e < EE; e++) {
#pragma unroll
            for (int o = 16; o; o >>= 1) acc[e] += __shfl_xor_sync(0xffffffffu, acc[e], o);
        }
        if (lane == 0) {
            float m = -1e30f; int best = 0;
#pragma unroll
            for (int e = 0; e < EE; e++) {
                float l = acc[e] + br[e];
                acc[e] = l;
                if (l > m) { m = l; best = e; }
            }
            float s = 0.f;
#pragma unroll
            for (int e = 0; e < EE; e++) s += expf(acc[e] - m);
            g_expert[token] = best;
            g_prob[token]   = 1.f / s;
            g_pos[token]    = atomicAdd(&g_counts[best], 1);
        }
    } else {
        // ---- W1 convert (no deps): 8192 blocks x 256 thr x 8 elems ----
        int wb = b - TT / 8;                 // 0..8191
        size_t i8 = (((size_t)wb * 256) + threadIdx.x) * 8;
        conv8(W1, T1, i8);
    }
}

__global__ void scan_kernel() {
    int s = 0;
#pragma unroll
    for (int e = 0; e < EE; e++) { g_off[e] = s; s += g_counts[e]; }
    g_off[EE] = s;
}

// gather tokens expert-contiguous, fp32 -> fp16. One token per block.
__global__ void gather_split_kernel(const float* __restrict__ x) {
    int token = blockIdx.x;
    int dst = g_off[g_expert[token]] + g_pos[token];
    if (threadIdx.x == 0) g_perm[dst] = token;
    const float4* s = (const float4*)(x + (size_t)token * DD);
    uint2* dh = (uint2*)(g_Xh + (size_t)dst * DD);
    for (int i = threadIdx.x; i < DD / 4; i += blockDim.x) {
        float4 v = s[i];
        __half2 h0, h1;
        h0.x = __float2half_rn(v.x); h0.y = __float2half_rn(v.y);
        h1.x = __float2half_rn(v.z); h1.y = __float2half_rn(v.w);
        uint2 ph;
        ph.x = *(uint32_t*)&h0; ph.y = *(uint32_t*)&h1;
        dh[i] = ph;
    }
}

// ---------------- grouped fp16 HMMA GEMM, 4-stage cp.async ring --------------
// Block tile 128(M) x 256(N), BK=64. 8 warps in 2(M) x 4(N), each warp 64x64.
// A: [rows][K] row-major, 128B smem rows, non-trans ldmatrix.
// B: native [K][NOUT]; smem tile [64 x 512B], trans ldmatrix (no pre-transpose).
// FIRST kernel carries an extra z-plane (blockIdx.z == EE) that stream-converts
// W2 fp32->fp16; those blocks are scheduled last and fill GEMM1's wave tail.
static constexpr int BM = 128, BN = 256, BK = 64;
static constexpr int A_T = BM * 128;                    // 16 KB A tile
static constexpr int B_T = BK * 512;                    // 32 KB B tile
static constexpr int STAGE = A_T + B_T;                 // 48 KB
static constexpr int SMEM_GEMM = 4 * STAGE;             // 192 KB

template <int K, int NOUT, bool FIRST>
__global__ void __launch_bounds__(256, 1) gemm_mma(
    const __half* __restrict__ A,
    const __half* __restrict__ B_all,
    const float* __restrict__ ball,
    __half* __restrict__ OutH,
    float* __restrict__ OutF,
    const float* __restrict__ W2src,
    __half* __restrict__ W2dst)
{
    constexpr int KC = K / BK;

    if (FIRST && blockIdx.z == EE) {
        // ---- W2 convert plane: 512 blocks x 256 thr x 16 iters x 8 elems ----
        int bid = blockIdx.x + (int)gridDim.x * blockIdx.y;   // 0..511
        size_t base = ((size_t)bid * 256 + threadIdx.x) * 8;
#pragma unroll
        for (int it = 0; it < 16; it++)
            conv8(W2src, W2dst, base + (size_t)it * (512 * 256 * 8));
        return;
    }

    int e = blockIdx.z;
    int rowBeg = g_off[e], rowEnd = g_off[e + 1];
    int row0 = rowBeg + blockIdx.y * BM;
    if (row0 >= rowEnd) return;
    int n0 = blockIdx.x * BN;

    const __half* BE = B_all + (size_t)e * K * NOUT;
    const float* bias = ball + (size_t)e * NOUT;

    extern __shared__ __align__(128) char smem[];
    uint32_t sb = smem_u32(smem);

    int tid = threadIdx.x;
    int wid = tid >> 5, lane = tid & 31;
    int warpM = wid & 1, warpN = wid >> 1;

    // ---- per-thread gmem->smem geometry (chunk-invariant) ----
    uint32_t smoA[4]; int rkA[4];
#pragma unroll
    for (int j = 0; j < 4; j++) {
        int id = tid + j * 256;
        int r = id >> 3, c = id & 7;
        smoA[j] = (uint32_t)(r * 128 + ((c ^ (r & 7)) << 4));
        rkA[j] = r * K + c * 8;
    }
    // B: 2048 chunks of 16B over [64 rows][32 chunks]
    uint32_t smoB[8]; int rkB[8];
#pragma unroll
    for (int j = 0; j < 8; j++) {
        int id = tid + j * 256;
        int r = id >> 5, c = id & 31;
        smoB[j] = (uint32_t)(r * 512 + ((c ^ (r & 7)) << 4));
        rkB[j] = r * NOUT + c * 8;
    }

    // ---- ldmatrix per-thread geometry ----
    int rA  = warpM * 64 + (lane & 15);
    int cxA = lane >> 4;
    int sAx = rA & 7;
    // B (trans): lanes 0-7 k0-7, 8-15 k8-15, 16-23 k0-7(+n8), 24-31 k8-15(+n8)
    int bRow = (lane & 7) + (((lane >> 3) & 1) << 3);   // 0..15
    uint32_t bByte = (uint32_t)bRow * 512;
    int c16b = warpN * 8 + (lane >> 4);                 // +2*j per n16-tile
    int sBx = lane & 7;

    float acc[4][8][4];
#pragma unroll
    for (int i = 0; i < 4; i++)
#pragma unroll
        for (int j = 0; j < 8; j++)
#pragma unroll
            for (int q = 0; q < 4; q++) acc[i][j][q] = 0.f;

    size_t aRowOff = (size_t)row0 * K;

    auto issue = [&](int cn) {
        if (cn < KC) {
            int kk = cn * BK;
            uint32_t st = sb + (uint32_t)((cn & 3) * STAGE);
            const __half* Ap = A + aRowOff + kk;
            const __half* Bp = BE + (size_t)kk * NOUT + n0;
#pragma unroll
            for (int j = 0; j < 4; j++) cp16(st + smoA[j], Ap + rkA[j]);
#pragma unroll
            for (int j = 0; j < 8; j++) cp16(st + A_T + smoB[j], Bp + rkB[j]);
        }
        cp_commit();   // uniform group count even in the tail
    };

    issue(0); issue(1); issue(2);

    for (int c = 0; c < KC; c++) {
        cp_wait2();                    // stage c complete
        __syncthreads();               // visible to all warps; stage c-1 free
        issue(c + 3);                  // overwrites stage c-1's buffer
        uint32_t st = sb + (uint32_t)((c & 3) * STAGE);
        uint32_t aSm = st, bSm = st + A_T;
#pragma unroll
        for (int ks = 0; ks < 4; ks++) {
            uint32_t aro = (uint32_t)((((ks << 1) + cxA) ^ sAx) << 4);
            uint32_t af[4][4];
#pragma unroll
            for (int i = 0; i < 4; i++) {
                uint32_t roff = (uint32_t)((rA + i * 16) * 128) + aro;
                LDSM4(af[i][0], af[i][1], af[i][2], af[i][3], aSm + roff);
            }
            uint32_t bf[4][4];
            uint32_t bks = bSm + (uint32_t)(ks * 8192) + bByte;
#pragma unroll
            for (int j = 0; j < 4; j++) {
                uint32_t addr = bks + (uint32_t)(((c16b + 2 * j) ^ sBx) << 4);
                LDSM4T(bf[j][0], bf[j][1], bf[j][2], bf[j][3], addr);
            }
#pragma unroll
            for (int i = 0; i < 4; i++)
#pragma unroll
                for (int j = 0; j < 4; j++) {
                    MMA16816(acc[i][2 * j],     af[i], bf[j][0], bf[j][1]);
                    MMA16816(acc[i][2 * j + 1], af[i], bf[j][2], bf[j][3]);
                }
        }
    }

    // ---- epilogue ----
    int mb = row0 + warpM * 64;
    int nb = n0 + warpN * 64;
    int lr = lane >> 2, lc = (lane & 3) * 2;
    float2 blv[8];
#pragma unroll
    for (int j = 0; j < 8; j++) {
        int col = nb + j * 8 + lc;
        blv[j].x = __ldg(bias + col);
        blv[j].y = __ldg(bias + col + 1);
    }
#pragma unroll
    for (int i = 0; i < 4; i++) {
#pragma unroll
        for (int h = 0; h < 2; h++) {
            int row = mb + i * 16 + lr + h * 8;
            if (row < rowEnd) {
                if (FIRST) {
                    uint32_t* dh = (uint32_t*)(OutH + (size_t)row * NOUT);
#pragma unroll
                    for (int j = 0; j < 8; j++) {
                        int col = nb + j * 8 + lc;
                        float v0 = acc[i][j][2 * h]     + blv[j].x;
                        float v1 = acc[i][j][2 * h + 1] + blv[j].y;
                        v0 = fmaxf(v0, 0.f); v1 = fmaxf(v1, 0.f);
                        __half2 hh;
                        hh.x = __float2half_rn(v0); hh.y = __float2half_rn(v1);
                        dh[col >> 1] = *(uint32_t*)&hh;
                    }
                } else {
                    int tok = g_perm[row];
                    float p = g_prob[tok];
                    float2* dst = (float2*)(OutF + (size_t)tok * NOUT);
#pragma unroll
                    for (int j = 0; j < 8; j++) {
                        int col = nb + j * 8 + lc;
                        float2 o;
                        o.x = (acc[i][j][2 * h]     + blv[j].x) * p;
                        o.y = (acc[i][j][2 * h + 1] + blv[j].y) * p;
                        dst[col >> 1] = o;
                    }
                }
            }
        }
    }
}

// ---------------- entry ----------------
extern "C" void kernel_launch(void* const* d_in, const int* in_sizes, int n_in,
                              void* d_out, int out_size) {
    const float* x  = (const float*)d_in[0];
    const float* Wr = (const float*)d_in[1];
    const float* br = (const float*)d_in[2];
    const float* W1 = (const float*)d_in[3];
    const float* b1 = (const float*)d_in[4];
    const float* W2 = (const float*)d_in[5];
    const float* b2 = (const float*)d_in[6];
    float* out = (float*)d_out;

    __half *Xh, *Hh, *W1h, *W2h;
    cudaGetSymbolAddress((void**)&Xh, g_Xh);
    cudaGetSymbolAddress((void**)&Hh, g_Hh);
    cudaGetSymbolAddress((void**)&W1h, g_W1h);
    cudaGetSymbolAddress((void**)&W2h, g_W2h);

    cudaFuncSetAttribute(gemm_mma<DD, HH, true>,  cudaFuncAttributeMaxDynamicSharedMemorySize, SMEM_GEMM);
    cudaFuncSetAttribute(gemm_mma<HH, DD, false>, cudaFuncAttributeMaxDynamicSharedMemorySize, SMEM_GEMM);

    zero_counts_kernel<<<1, 32>>>();
    // router blocks (1024) + W1-convert blocks (8192): one launch
    router_wconv_kernel<<<TT / 8 + 8192, 256>>>(x, Wr, br, W1, W1h);
    scan_kernel<<<1, 1>>>();
    gather_split_kernel<<<TT, 256>>>(x);

    // GEMM1 + trailing W2-convert plane (z == EE)
    dim3 g1(HH / BN, TT / BM, EE + 1);
    gemm_mma<DD, HH, true><<<g1, 256, SMEM_GEMM>>>(Xh, W1h, b1, Hh, nullptr, W2, W2h);
    dim3 g2(DD / BN, TT / BM, EE);
    gemm_mma<HH, DD, false><<<g2, 256, SMEM_GEMM>>>(Hh, W2h, b2, nullptr, out, nullptr, nullptr);
}